// round 1
// baseline (speedup 1.0000x reference)
#include <cuda_runtime.h>
#include <math.h>

#define BB 8
#define NVV 500
#define NOO 1500
#define DVV 512
#define DOO 32
#define HH 128
#define EPSF 1e-5f

// ---------------- scratch (device globals; no allocation allowed) ----------------
__device__ float g_hv [BB*NVV*HH];
__device__ float g_ho [BB*NOO*HH];
__device__ float g_v  [BB*NVV*HH];
__device__ float g_o  [BB*NOO*HH];
__device__ float g_cv [BB*NVV*HH];
__device__ float g_co [BB*NOO*HH];
__device__ float g_m1v[BB*NVV*HH];
__device__ float g_m1o[BB*NOO*HH];
__device__ float g_vs [BB*NVV*HH];
__device__ float g_vis[BB*NVV*HH];
__device__ float g_obj[BB*NOO*HH];
__device__ float g_s1v[BB*NVV];
__device__ float g_s2v[BB*NVV];
__device__ float g_s1o[BB*NOO];
__device__ float g_s2o[BB*NOO];
__device__ float g_smaxv[BB];
__device__ float g_smaxo[BB];
__device__ float g_rvsum[BB*NVV];
__device__ float g_rv  [BB*NVV];
__device__ float g_to  [BB*NOO];

// ---------------- generic batched fp32 GEMM ----------------
// C[b,m,n] = act( rowscale[b,m] * sum_k Aop[b,m,k]*Bm[b,k,n] + bias[n] + res[b,m,n] )
// TRANSA: A stored as (K, M) per batch (used for A^T @ B).
template<bool TRANSA>
__global__ void gemm_kernel(const float* __restrict__ A,
                            const float* __restrict__ Bm,
                            float* __restrict__ C,
                            const float* __restrict__ bias,
                            const float* __restrict__ res,
                            const float* __restrict__ rowscale,
                            int M, int N, int K,
                            long sA, long sB, long sC,
                            int relu)
{
    const int BM = 64, BN = 64, BK = 16;
    __shared__ float As[BK * 65];   // padded stride 65 -> conflict-free
    __shared__ float Bs[BK * BN];

    int b  = blockIdx.z;
    const float* Ab = A  + (long)b * sA;
    const float* Bb = Bm + (long)b * sB;
    int m0 = blockIdx.y * BM;
    int n0 = blockIdx.x * BN;
    int t  = threadIdx.x;
    int tn = t & 15;        // 0..15
    int tm = t >> 4;        // 0..15

    float acc[4][4];
    #pragma unroll
    for (int i = 0; i < 4; i++)
        #pragma unroll
        for (int j = 0; j < 4; j++) acc[i][j] = 0.f;

    for (int k0 = 0; k0 < K; k0 += BK) {
        // load A tile
        #pragma unroll
        for (int p = 0; p < 4; p++) {
            int l = t + p * 256;
            int m, k;
            if (TRANSA) { m = l & 63; k = l >> 6; }
            else        { k = l & 15; m = l >> 4; }
            int gm = m0 + m, gk = k0 + k;
            float val = 0.f;
            if (gm < M && gk < K)
                val = TRANSA ? Ab[(long)gk * M + gm] : Ab[(long)gm * K + gk];
            As[k * 65 + m] = val;
        }
        // load B tile
        #pragma unroll
        for (int p = 0; p < 4; p++) {
            int l = t + p * 256;
            int n = l & 63, k = l >> 6;
            int gn = n0 + n, gk = k0 + k;
            float val = 0.f;
            if (gn < N && gk < K) val = Bb[(long)gk * N + gn];
            Bs[k * BN + n] = val;
        }
        __syncthreads();

        #pragma unroll
        for (int kk = 0; kk < BK; kk++) {
            float ra[4];
            #pragma unroll
            for (int i = 0; i < 4; i++) ra[i] = As[kk * 65 + tm * 4 + i];
            float4 rb4 = *(const float4*)&Bs[kk * BN + tn * 4];
            float rb[4] = {rb4.x, rb4.y, rb4.z, rb4.w};
            #pragma unroll
            for (int i = 0; i < 4; i++)
                #pragma unroll
                for (int j = 0; j < 4; j++)
                    acc[i][j] += ra[i] * rb[j];
        }
        __syncthreads();
    }

    #pragma unroll
    for (int i = 0; i < 4; i++) {
        int row = m0 + tm * 4 + i;
        if (row >= M) continue;
        float scale = rowscale ? rowscale[b * M + row] : 1.f;
        #pragma unroll
        for (int j = 0; j < 4; j++) {
            int col = n0 + tn * 4 + j;
            if (col >= N) continue;
            float v = acc[i][j] * scale;
            if (bias) v += bias[col];
            if (res)  v += res[(long)b * sC + (long)row * N + col];
            if (relu) v = v > 0.f ? v : 0.f;
            C[(long)b * sC + (long)row * N + col] = v;
        }
    }
}

// ---------------- fused masked-softmax attention:  out = relu(softmax(mask(e)) @ h) ----------------
// e_ij = lrelu(s1_i + s2_j, 0.2); mask adj>0; m_i = lrelu(s1_i + max_j s2_j) (safe upper bound)
// block: 16 rows x 128 features, 256 threads. grid: (ceil(N/16), B)
#define ATTN_SMEM ((128*132 + 16*128 + 256 + 16) * 4)
__global__ void attn_kernel(const float* __restrict__ hbuf,
                            const float* __restrict__ adj,
                            const float* __restrict__ s1,
                            const float* __restrict__ s2,
                            const float* __restrict__ smax,
                            float* __restrict__ out,
                            int N)
{
    extern __shared__ float sm[];
    float* hs   = sm;                    // [128][132] transposed h chunk
    float* ws   = sm + 128 * 132;        // [16][128]
    float* zp   = ws + 16 * 128;         // [256]
    float* zrow = zp + 256;              // [16]

    int b  = blockIdx.y;
    int i0 = blockIdx.x * 16;
    int t  = threadIdx.x;
    int f  = t & 127;
    int g  = t >> 7;                      // 0/1 -> rows g*8..g*8+7

    const float* hb   = hbuf + (long)b * N * HH;
    const float* adjb = adj  + (long)b * N * N;
    const float* s2b  = s2   + (long)b * N;

    float acc[8];
    #pragma unroll
    for (int r = 0; r < 8; r++) acc[r] = 0.f;
    if (t < 16) zrow[t] = 0.f;

    int rw    = t >> 4;                   // w-phase row 0..15
    int js    = (t & 15) * 8;             // w-phase j-segment
    int row_w = i0 + rw;
    float s1r = 0.f, mrow = 0.f;
    float mb  = smax[b];
    if (row_w < N) {
        s1r = s1[(long)b * N + row_w];
        float x = s1r + mb;
        mrow = x > 0.f ? x : 0.2f * x;
    }
    __syncthreads();

    for (int j0 = 0; j0 < N; j0 += 128) {
        int JC = N - j0; if (JC > 128) JC = 128;

        // stage h chunk transposed: hs[f][j]
        for (int l = t; l < 128 * 128; l += 256) {
            int ff = l & 127, jj = l >> 7;
            float v = 0.f;
            if (jj < JC) v = hb[(long)(j0 + jj) * HH + ff];
            hs[ff * 132 + jj] = v;
        }

        // compute softmax weights for 16x128 tile
        float zloc = 0.f;
        if (row_w < N) {
            const float* arow = adjb + (long)row_w * N + j0;
            #pragma unroll
            for (int i = 0; i < 8; i++) {
                int j = js + i;
                float w = 0.f;
                if (j < JC) {
                    float a = arow[j];
                    if (a > 0.f) {
                        float x = s1r + s2b[j0 + j];
                        float e = x > 0.f ? x : 0.2f * x;
                        w = __expf(e - mrow);
                    }
                }
                ws[rw * 128 + j] = w;
                zloc += w;
            }
        } else {
            #pragma unroll
            for (int i = 0; i < 8; i++) ws[rw * 128 + js + i] = 0.f;
        }
        zp[t] = zloc;
        __syncthreads();

        if (t < 16) {
            float z = 0.f;
            #pragma unroll
            for (int s = 0; s < 16; s++) z += zp[t * 16 + s];
            zrow[t] += z;
        }

        // accumulate: acc[r] += sum_j w[r][j] * h[j][f]
        for (int j = 0; j < 128; j += 4) {
            float4 hv = *(const float4*)&hs[f * 132 + j];
            #pragma unroll
            for (int r = 0; r < 8; r++) {
                float4 wv = *(const float4*)&ws[(g * 8 + r) * 128 + j];
                acc[r] += wv.x * hv.x + wv.y * hv.y + wv.z * hv.z + wv.w * hv.w;
            }
        }
        __syncthreads();
    }

    #pragma unroll
    for (int r = 0; r < 8; r++) {
        int row = i0 + g * 8 + r;
        if (row < N) {
            float v = acc[r] / zrow[g * 8 + r];
            v = v > 0.f ? v : 0.f;   // relu(gat(...))
            out[(long)b * N * HH + (long)row * HH + f] = v;
        }
    }
}

// ---------------- small helper kernels ----------------
__global__ void scores_kernel(const float* __restrict__ h,
                              const float* __restrict__ a1,
                              const float* __restrict__ a2,
                              float* __restrict__ s1, float* __restrict__ s2, int N)
{
    int b = blockIdx.y;
    int warp = threadIdx.x >> 5, lane = threadIdx.x & 31;
    int row = blockIdx.x * 4 + warp;
    if (row >= N) return;
    const float* hr = h + ((long)b * N + row) * HH;
    float p1 = 0.f, p2 = 0.f;
    #pragma unroll
    for (int i = 0; i < 4; i++) {
        float hv = hr[lane + 32 * i];
        p1 += hv * a1[lane + 32 * i];
        p2 += hv * a2[lane + 32 * i];
    }
    #pragma unroll
    for (int off = 16; off; off >>= 1) {
        p1 += __shfl_xor_sync(0xffffffffu, p1, off);
        p2 += __shfl_xor_sync(0xffffffffu, p2, off);
    }
    if (lane == 0) {
        s1[(long)b * N + row] = p1;
        s2[(long)b * N + row] = p2;
    }
}

__global__ void smax_kernel(const float* __restrict__ s2, float* __restrict__ smax, int N)
{
    __shared__ float red[256];
    int b = blockIdx.x;
    float m = -1e30f;
    for (int i = threadIdx.x; i < N; i += 256) m = fmaxf(m, s2[(long)b * N + i]);
    red[threadIdx.x] = m;
    __syncthreads();
    for (int s = 128; s > 0; s >>= 1) {
        if (threadIdx.x < s) red[threadIdx.x] = fmaxf(red[threadIdx.x], red[threadIdx.x + s]);
        __syncthreads();
    }
    if (threadIdx.x == 0) smax[b] = red[0];
}

__global__ void colsum_kernel(const float* __restrict__ A, float* __restrict__ sums)
{
    // grid (2, B, 12): sums[b,v] += sum over 125 o's of A[b,o,v]
    int v = blockIdx.x * 256 + threadIdx.x;
    if (v >= NVV) return;
    int b = blockIdx.y, seg = blockIdx.z;
    const float* Ab = A + (long)b * NOO * NVV;
    int o0 = seg * 125;
    float s = 0.f;
    #pragma unroll 4
    for (int o = o0; o < o0 + 125; o++) s += Ab[(long)o * NVV + v];
    atomicAdd(&sums[b * NVV + v], s);
}

__global__ void rvfin_kernel(const float* __restrict__ sums, float* __restrict__ rv, int n)
{
    int i = blockIdx.x * 256 + threadIdx.x;
    if (i < n) rv[i] = 1.f / (sums[i] + EPSF);
}

__global__ void rowsum_kernel(const float* __restrict__ A, const float* __restrict__ rv,
                              float* __restrict__ to_)
{
    int warp = threadIdx.x >> 5, lane = threadIdx.x & 31;
    int o = blockIdx.x * 8 + warp;
    int b = blockIdx.y;
    if (o >= NOO) return;
    const float* Ar  = A + ((long)b * NOO + o) * NVV;
    const float* rvb = rv + b * NVV;
    float s = 0.f;
    for (int v = lane; v < NVV; v += 32) s += Ar[v] * rvb[v];
    #pragma unroll
    for (int off = 16; off; off >>= 1) s += __shfl_xor_sync(0xffffffffu, s, off);
    if (lane == 0) to_[b * NOO + o] = 1.f / (s + EPSF);
}

__global__ void scale_kernel(const float* __restrict__ x, const float* __restrict__ rv,
                             float* __restrict__ y, int n)
{
    int i = blockIdx.x * 256 + threadIdx.x;
    if (i < n) y[i] = x[i] * rv[i >> 7];   // row = i / HH, rv laid out (B,NV)
}

// ---------------- host orchestration ----------------
static void launch_gemm(bool transA, const float* A, const float* Bm, float* C,
                        const float* bias, const float* res, const float* rowscale,
                        int M, int N, int K, long sA, long sB, long sC, int relu)
{
    dim3 grid((N + 63) / 64, (M + 63) / 64, BB);
    if (transA)
        gemm_kernel<true><<<grid, 256>>>(A, Bm, C, bias, res, rowscale, M, N, K, sA, sB, sC, relu);
    else
        gemm_kernel<false><<<grid, 256>>>(A, Bm, C, bias, res, rowscale, M, N, K, sA, sB, sC, relu);
}

extern "C" void kernel_launch(void* const* d_in, const int* in_sizes, int n_in,
                              void* d_out, int out_size)
{
    const float* vis_memory = (const float*)d_in[0];
    const float* obj_memory = (const float*)d_in[1];
    const float* vis_adj    = (const float*)d_in[2];
    const float* obj_adj    = (const float*)d_in[3];
    const float* A_OV       = (const float*)d_in[4];
    const float* Wv1  = (const float*)d_in[5];
    const float* av1a = (const float*)d_in[6];
    const float* av1b = (const float*)d_in[7];
    const float* Wv2  = (const float*)d_in[8];
    const float* av2a = (const float*)d_in[9];
    const float* av2b = (const float*)d_in[10];
    const float* Wo1  = (const float*)d_in[11];
    const float* ao1a = (const float*)d_in[12];
    const float* ao1b = (const float*)d_in[13];
    const float* Wo2  = (const float*)d_in[14];
    const float* ao2a = (const float*)d_in[15];
    const float* ao2b = (const float*)d_in[16];
    const float* g2o_W1 = (const float*)d_in[17];
    const float* g2o_b1 = (const float*)d_in[18];
    const float* g2o_W2 = (const float*)d_in[19];
    const float* g2o_b2 = (const float*)d_in[20];
    const float* o2g_W1 = (const float*)d_in[21];
    const float* o2g_b1 = (const float*)d_in[22];
    const float* o2g_W2 = (const float*)d_in[23];
    const float* o2g_b2 = (const float*)d_in[24];
    const float* img_W = (const float*)d_in[25];
    const float* img_b = (const float*)d_in[26];
    const float* obj_W = (const float*)d_in[27];
    const float* obj_b = (const float*)d_in[28];

    float *p_hv, *p_ho, *p_v, *p_o, *p_cv, *p_co, *p_m1v, *p_m1o, *p_vs, *p_vis, *p_obj;
    float *p_s1v, *p_s2v, *p_s1o, *p_s2o, *p_smaxv, *p_smaxo, *p_rvsum, *p_rv, *p_to;
    cudaGetSymbolAddress((void**)&p_hv,  g_hv);
    cudaGetSymbolAddress((void**)&p_ho,  g_ho);
    cudaGetSymbolAddress((void**)&p_v,   g_v);
    cudaGetSymbolAddress((void**)&p_o,   g_o);
    cudaGetSymbolAddress((void**)&p_cv,  g_cv);
    cudaGetSymbolAddress((void**)&p_co,  g_co);
    cudaGetSymbolAddress((void**)&p_m1v, g_m1v);
    cudaGetSymbolAddress((void**)&p_m1o, g_m1o);
    cudaGetSymbolAddress((void**)&p_vs,  g_vs);
    cudaGetSymbolAddress((void**)&p_vis, g_vis);
    cudaGetSymbolAddress((void**)&p_obj, g_obj);
    cudaGetSymbolAddress((void**)&p_s1v, g_s1v);
    cudaGetSymbolAddress((void**)&p_s2v, g_s2v);
    cudaGetSymbolAddress((void**)&p_s1o, g_s1o);
    cudaGetSymbolAddress((void**)&p_s2o, g_s2o);
    cudaGetSymbolAddress((void**)&p_smaxv, g_smaxv);
    cudaGetSymbolAddress((void**)&p_smaxo, g_smaxo);
    cudaGetSymbolAddress((void**)&p_rvsum, g_rvsum);
    cudaGetSymbolAddress((void**)&p_rv,  g_rv);
    cudaGetSymbolAddress((void**)&p_to,  g_to);

    cudaFuncSetAttribute(attn_kernel, cudaFuncAttributeMaxDynamicSharedMemorySize, ATTN_SMEM);

    // --- cross-adjacency normalizers: rv[b,v], to[b,o] ---
    cudaMemsetAsync(p_rvsum, 0, BB * NVV * sizeof(float));
    colsum_kernel<<<dim3(2, BB, 12), 256>>>(A_OV, p_rvsum);
    rvfin_kernel<<<(BB * NVV + 255) / 256, 256>>>(p_rvsum, p_rv, BB * NVV);
    rowsum_kernel<<<dim3((NOO + 7) / 8, BB), 256>>>(A_OV, p_rv, p_to);

    for (int round = 0; round < 2; round++) {
        const float* xv  = (round == 0) ? vis_memory : p_vis;
        const float* xo  = (round == 0) ? obj_memory : p_obj;
        int Kv           = (round == 0) ? DVV : HH;
        int Ko           = (round == 0) ? DOO : HH;
        const float* Wv  = (round == 0) ? Wv1  : Wv2;
        const float* ava = (round == 0) ? av1a : av2a;
        const float* avb = (round == 0) ? av1b : av2b;
        const float* Wo  = (round == 0) ? Wo1  : Wo2;
        const float* aoa = (round == 0) ? ao1a : ao2a;
        const float* aob = (round == 0) ? ao1b : ao2b;

        // h = x @ W
        launch_gemm(false, xv, Wv, p_hv, nullptr, nullptr, nullptr,
                    NVV, HH, Kv, (long)NVV * Kv, 0, (long)NVV * HH, 0);
        launch_gemm(false, xo, Wo, p_ho, nullptr, nullptr, nullptr,
                    NOO, HH, Ko, (long)NOO * Ko, 0, (long)NOO * HH, 0);

        // attention scores + per-batch max
        scores_kernel<<<dim3((NVV + 3) / 4, BB), 128>>>(p_hv, ava, avb, p_s1v, p_s2v, NVV);
        scores_kernel<<<dim3((NOO + 3) / 4, BB), 128>>>(p_ho, aoa, aob, p_s1o, p_s2o, NOO);
        smax_kernel<<<BB, 256>>>(p_s2v, p_smaxv, NVV);
        smax_kernel<<<BB, 256>>>(p_s2o, p_smaxo, NOO);

        // fused masked softmax @ h, with relu
        attn_kernel<<<dim3((NVV + 15) / 16, BB), 256, ATTN_SMEM>>>(
            p_hv, vis_adj, p_s1v, p_s2v, p_smaxv, p_v, NVV);
        attn_kernel<<<dim3((NOO + 15) / 16, BB), 256, ATTN_SMEM>>>(
            p_ho, obj_adj, p_s1o, p_s2o, p_smaxo, p_o, NOO);

        // cv = rv ⊙ (A^T @ o)   (A is (NO,NV) per batch)
        launch_gemm(true, A_OV, p_o, p_cv, nullptr, nullptr, p_rv,
                    NVV, HH, NOO, (long)NOO * NVV, (long)NOO * HH, (long)NVV * HH, 0);
        // vis = v + mlp(cv; o2g)
        launch_gemm(false, p_cv, o2g_W1, p_m1v, o2g_b1, nullptr, nullptr,
                    NVV, HH, HH, (long)NVV * HH, 0, (long)NVV * HH, 1);
        launch_gemm(false, p_m1v, o2g_W2, p_vis, o2g_b2, p_v, nullptr,
                    NVV, HH, HH, (long)NVV * HH, 0, (long)NVV * HH, 0);

        // co = to ⊙ (A @ (rv ⊙ v))
        scale_kernel<<<(BB * NVV * HH + 255) / 256, 256>>>(p_v, p_rv, p_vs, BB * NVV * HH);
        launch_gemm(false, A_OV, p_vs, p_co, nullptr, nullptr, p_to,
                    NOO, HH, NVV, (long)NOO * NVV, (long)NVV * HH, (long)NOO * HH, 0);
        // obj = o + mlp(co; g2o)
        launch_gemm(false, p_co, g2o_W1, p_m1o, g2o_b1, nullptr, nullptr,
                    NOO, HH, HH, (long)NOO * HH, 0, (long)NOO * HH, 1);
        launch_gemm(false, p_m1o, g2o_W2, p_obj, g2o_b2, p_o, nullptr,
                    NOO, HH, HH, (long)NOO * HH, 0, (long)NOO * HH, 0);
    }

    // output projections: vis_out first, then obj_out (tuple flatten order)
    float* out_vis = (float*)d_out;
    float* out_obj = out_vis + (long)BB * NVV * DVV;
    launch_gemm(false, p_vis, img_W, out_vis, img_b, nullptr, nullptr,
                NVV, DVV, HH, (long)NVV * HH, 0, (long)NVV * DVV, 0);
    launch_gemm(false, p_obj, obj_W, out_obj, obj_b, nullptr, nullptr,
                NOO, DOO, HH, (long)NOO * HH, 0, (long)NOO * DOO, 0);
}

// round 2
// speedup vs baseline: 1.1464x; 1.1464x over previous
#include <cuda_runtime.h>
#include <math.h>

#define BB 8
#define NVV 500
#define NOO 1500
#define DVV 512
#define DOO 32
#define HH 128
#define EPSF 1e-5f

// ---------------- scratch ----------------
__device__ float g_hv [BB*NVV*HH];
__device__ float g_ho [BB*NOO*HH];
__device__ float g_v  [BB*NVV*HH];
__device__ float g_o  [BB*NOO*HH];
__device__ float g_cv [BB*NVV*HH];
__device__ float g_co [BB*NOO*HH];
__device__ float g_m1v[BB*NVV*HH];
__device__ float g_m1o[BB*NOO*HH];
__device__ float g_vs [BB*NVV*HH];
__device__ float g_vis[BB*NVV*HH];
__device__ float g_obj[BB*NOO*HH];
__device__ float g_s1v[BB*NVV];
__device__ float g_s2v[BB*NVV];
__device__ float g_s1o[BB*NOO];
__device__ float g_s2o[BB*NOO];
__device__ float g_smaxv[BB];
__device__ float g_smaxo[BB];
__device__ float g_rvsum[BB*NVV];
__device__ float g_rv  [BB*NVV];
__device__ float g_to  [BB*NOO];

// ---------------- tf32 mma helpers ----------------
__device__ __forceinline__ unsigned cvt_tf32(float x) {
    unsigned r; asm("cvt.rna.tf32.f32 %0, %1;" : "=r"(r) : "f"(x)); return r;
}
__device__ __forceinline__ void mma8(float* d, const unsigned* a, const unsigned* b) {
    asm volatile("mma.sync.aligned.m16n8k8.row.col.f32.tf32.tf32.f32 "
                 "{%0,%1,%2,%3},{%4,%5,%6,%7},{%8,%9},{%0,%1,%2,%3};"
                 : "+f"(d[0]), "+f"(d[1]), "+f"(d[2]), "+f"(d[3])
                 : "r"(a[0]), "r"(a[1]), "r"(a[2]), "r"(a[3]), "r"(b[0]), "r"(b[1]));
}

// ---------------- tf32 tensor-core GEMM ----------------
// C[b,m,n] = act( rowscale[b,m]*sum_k Aop[b,m,k]*B[b,k,n] + bias[n] + res[b,m,n] )
// block tile 128x64, BK=16, 256 threads (8 warps: 4m x 2n), warp tile 32x32.
#define GBM 128
#define GBN 64
#define GBK 16
#define SAP 136   // As stride (== 8 mod 32 -> conflict-free frag loads)
#define SBP 72    // Bs stride (== 8 mod 32)

template<bool TRANSA>
__global__ void __launch_bounds__(256) gemm_tc(const float* __restrict__ A,
                                               const float* __restrict__ Bm,
                                               float* __restrict__ C,
                                               const float* __restrict__ bias,
                                               const float* __restrict__ res,
                                               const float* __restrict__ rowscale,
                                               int M, int N, int K,
                                               long sA, long sB, long sC, int relu)
{
    __shared__ unsigned As[GBK * SAP];
    __shared__ unsigned Bs[GBK * SBP];

    int b = blockIdx.z;
    const float* Ab = A  + (long)b * sA;
    const float* Bb = Bm + (long)b * sB;
    int m0 = blockIdx.y * GBM;
    int n0 = blockIdx.x * GBN;
    int t = threadIdx.x;
    int warp = t >> 5, lane = t & 31;
    int g = lane >> 2, tg = lane & 3;
    int wm = warp >> 1, wn = warp & 1;

    float acc[2][4][4];
    #pragma unroll
    for (int mi = 0; mi < 2; mi++)
        #pragma unroll
        for (int ni = 0; ni < 4; ni++)
            #pragma unroll
            for (int e = 0; e < 4; e++) acc[mi][ni][e] = 0.f;

    // tile-load thread mapping
    int am, ak;
    if (TRANSA) { ak = t >> 4; am = (t & 15) * 8; }   // A stored (K x M)
    else        { am = t >> 1; ak = (t & 1) * 8; }    // A stored (M x K)
    int bk = t >> 4, bn = (t & 15) * 4;

    float4 ra[2], rb;
    const float4 z4 = make_float4(0.f, 0.f, 0.f, 0.f);

    // prefetch tile 0
    {
        int k0 = 0;
        if (TRANSA) {
            bool kok = (k0 + ak) < K;
            long base = (long)(k0 + ak) * M;
            #pragma unroll
            for (int i = 0; i < 2; i++) {
                int gm = m0 + am + i * 4;
                ra[i] = (kok && gm < M) ? *(const float4*)&Ab[base + gm] : z4;
            }
        } else {
            int gm = m0 + am;
            #pragma unroll
            for (int i = 0; i < 2; i++) {
                int gk = k0 + ak + i * 4;
                ra[i] = (gm < M && gk < K) ? *(const float4*)&Ab[(long)gm * K + gk] : z4;
            }
        }
        int gk = k0 + bk, gn = n0 + bn;
        rb = (gk < K && gn < N) ? *(const float4*)&Bb[(long)gk * N + gn] : z4;
    }

    int ntiles = (K + GBK - 1) / GBK;
    for (int it = 0; it < ntiles; it++) {
        // store current tile to smem (with tf32 rounding)
        if (TRANSA) {
            #pragma unroll
            for (int i = 0; i < 2; i++) {
                uint4 u;
                u.x = cvt_tf32(ra[i].x); u.y = cvt_tf32(ra[i].y);
                u.z = cvt_tf32(ra[i].z); u.w = cvt_tf32(ra[i].w);
                *(uint4*)&As[ak * SAP + am + i * 4] = u;
            }
        } else {
            #pragma unroll
            for (int i = 0; i < 2; i++) {
                float v[4] = {ra[i].x, ra[i].y, ra[i].z, ra[i].w};
                #pragma unroll
                for (int e = 0; e < 4; e++)
                    As[(ak + i * 4 + e) * SAP + am] = cvt_tf32(v[e]);
            }
        }
        {
            uint4 u;
            u.x = cvt_tf32(rb.x); u.y = cvt_tf32(rb.y);
            u.z = cvt_tf32(rb.z); u.w = cvt_tf32(rb.w);
            *(uint4*)&Bs[bk * SBP + bn] = u;
        }
        __syncthreads();

        // prefetch next tile
        if (it + 1 < ntiles) {
            int k0 = (it + 1) * GBK;
            if (TRANSA) {
                bool kok = (k0 + ak) < K;
                long base = (long)(k0 + ak) * M;
                #pragma unroll
                for (int i = 0; i < 2; i++) {
                    int gm = m0 + am + i * 4;
                    ra[i] = (kok && gm < M) ? *(const float4*)&Ab[base + gm] : z4;
                }
            } else {
                int gm = m0 + am;
                #pragma unroll
                for (int i = 0; i < 2; i++) {
                    int gk = k0 + ak + i * 4;
                    ra[i] = (gm < M && gk < K) ? *(const float4*)&Ab[(long)gm * K + gk] : z4;
                }
            }
            int gk = k0 + bk, gn = n0 + bn;
            rb = (gk < K && gn < N) ? *(const float4*)&Bb[(long)gk * N + gn] : z4;
        }

        // compute
        #pragma unroll
        for (int kk = 0; kk < GBK; kk += 8) {
            unsigned af[2][4], bf[4][2];
            #pragma unroll
            for (int mi = 0; mi < 2; mi++) {
                int mb = wm * 32 + mi * 16 + g;
                af[mi][0] = As[(kk + tg) * SAP + mb];
                af[mi][1] = As[(kk + tg) * SAP + mb + 8];
                af[mi][2] = As[(kk + tg + 4) * SAP + mb];
                af[mi][3] = As[(kk + tg + 4) * SAP + mb + 8];
            }
            #pragma unroll
            for (int ni = 0; ni < 4; ni++) {
                int nb = wn * 32 + ni * 8 + g;
                bf[ni][0] = Bs[(kk + tg) * SBP + nb];
                bf[ni][1] = Bs[(kk + tg + 4) * SBP + nb];
            }
            #pragma unroll
            for (int mi = 0; mi < 2; mi++)
                #pragma unroll
                for (int ni = 0; ni < 4; ni++)
                    mma8(acc[mi][ni], af[mi], bf[ni]);
        }
        __syncthreads();
    }

    // epilogue
    #pragma unroll
    for (int mi = 0; mi < 2; mi++) {
        #pragma unroll
        for (int half = 0; half < 2; half++) {
            int row = m0 + wm * 32 + mi * 16 + g + half * 8;
            if (row >= M) continue;
            float scale = rowscale ? rowscale[b * M + row] : 1.f;
            #pragma unroll
            for (int ni = 0; ni < 4; ni++) {
                int col = n0 + wn * 32 + ni * 8 + tg * 2;
                if (col >= N) continue;
                float v0 = acc[mi][ni][half * 2 + 0] * scale;
                float v1 = acc[mi][ni][half * 2 + 1] * scale;
                if (bias) { v0 += bias[col]; v1 += bias[col + 1]; }
                long off = (long)b * sC + (long)row * N + col;
                if (res) { v0 += res[off]; v1 += res[off + 1]; }
                if (relu) { v0 = v0 > 0.f ? v0 : 0.f; v1 = v1 > 0.f ? v1 : 0.f; }
                *(float2*)&C[off] = make_float2(v0, v1);
            }
        }
    }
}

// ---------------- fused masked-softmax attention with tf32 mma ----------------
// out = relu( softmax(mask(lrelu(s1_i + s2_j))) @ h ), single pass using global
// max of s2 as a safe row-max. 64 rows x 128 feats per block, 128-j chunks.
#define AROWS 64
#define AJC 128
#define HS_S 136
#define WS_S 132
#define ATTN_SMEM_TC ((128*HS_S + AROWS*WS_S + AROWS) * 4)

__global__ void __launch_bounds__(256) attn_tc(const float* __restrict__ hbuf,
                                               const float* __restrict__ adj,
                                               const float* __restrict__ s1,
                                               const float* __restrict__ s2,
                                               const float* __restrict__ smax,
                                               float* __restrict__ out,
                                               int N)
{
    extern __shared__ unsigned smu[];
    unsigned* hs = smu;                       // [128][HS_S] tf32 of h chunk (j, f)
    unsigned* ws = smu + 128 * HS_S;          // [AROWS][WS_S] tf32 weights (r, j)
    float* zrow  = (float*)(ws + AROWS * WS_S);

    int b = blockIdx.y;
    int i0 = blockIdx.x * AROWS;
    int t = threadIdx.x;
    int warp = t >> 5, lane = t & 31;
    int g = lane >> 2, tg = lane & 3;

    const float* hb   = hbuf + (long)b * N * HH;
    const float* adjb = adj  + (long)b * N * N;
    const float* s2b  = s2   + (long)b * N;

    float acc[4][2][4];
    #pragma unroll
    for (int mi = 0; mi < 4; mi++)
        #pragma unroll
        for (int ni = 0; ni < 2; ni++)
            #pragma unroll
            for (int e = 0; e < 4; e++) acc[mi][ni][e] = 0.f;

    if (t < AROWS) zrow[t] = 0.f;

    // weight-producer role: 4 threads per row, 32 j's each
    int pr = t >> 2;
    int pj = (t & 3) * 32;
    int prow = i0 + pr;
    float s1r = 0.f, mrow = 0.f;
    if (prow < N) {
        s1r = s1[(long)b * N + prow];
        float x = s1r + smax[b];
        mrow = x > 0.f ? x : 0.2f * x;
    }

    // h stage role: warp-row + q*8, 4 floats per lane
    int hrow0 = t >> 5;
    int hf4 = (t & 31) * 4;

    for (int j0 = 0; j0 < N; j0 += AJC) {
        __syncthreads();   // smem free from previous chunk's mma reads

        // stage h chunk (coalesced LDG.128, conflict-free STS.128)
        #pragma unroll
        for (int q = 0; q < 16; q++) {
            int jj = hrow0 + q * 8;
            int gj = j0 + jj;
            uint4 u;
            if (gj < N) {
                float4 v = *(const float4*)&hb[(long)gj * HH + hf4];
                u.x = cvt_tf32(v.x); u.y = cvt_tf32(v.y);
                u.z = cvt_tf32(v.z); u.w = cvt_tf32(v.w);
            } else {
                u = make_uint4(0, 0, 0, 0);
            }
            *(uint4*)&hs[jj * HS_S + hf4] = u;
        }

        // compute weight tile + partial row sums
        float zl = 0.f;
        if (prow < N) {
            const float* arow = adjb + (long)prow * N + j0;
            #pragma unroll 8
            for (int q = 0; q < 32; q++) {
                int j = pj + q;
                int gj = j0 + j;
                float w = 0.f;
                if (gj < N) {
                    float a = arow[j];
                    if (a > 0.f) {
                        float x = s1r + s2b[gj];
                        float e = x > 0.f ? x : 0.2f * x;
                        w = __expf(e - mrow);
                    }
                }
                unsigned wu = cvt_tf32(w);
                ws[pr * WS_S + j] = wu;
                zl += __uint_as_float(wu);
            }
        } else {
            #pragma unroll 8
            for (int q = 0; q < 32; q++) ws[pr * WS_S + pj + q] = 0u;
        }
        zl += __shfl_down_sync(0xffffffffu, zl, 2);
        zl += __shfl_down_sync(0xffffffffu, zl, 1);
        if ((t & 3) == 0 && prow < N) zrow[pr] += zl;
        __syncthreads();

        // acc += ws(64x128) @ hs(128x128): m16n8k8 tf32
        #pragma unroll
        for (int kk = 0; kk < AJC; kk += 8) {
            unsigned af[4][4], bf[2][2];
            #pragma unroll
            for (int mi = 0; mi < 4; mi++) {
                int mb = mi * 16 + g;
                af[mi][0] = ws[mb * WS_S + kk + tg];
                af[mi][1] = ws[(mb + 8) * WS_S + kk + tg];
                af[mi][2] = ws[mb * WS_S + kk + tg + 4];
                af[mi][3] = ws[(mb + 8) * WS_S + kk + tg + 4];
            }
            #pragma unroll
            for (int ni = 0; ni < 2; ni++) {
                int nb = warp * 16 + ni * 8 + g;
                bf[ni][0] = hs[(kk + tg) * HS_S + nb];
                bf[ni][1] = hs[(kk + tg + 4) * HS_S + nb];
            }
            #pragma unroll
            for (int mi = 0; mi < 4; mi++)
                #pragma unroll
                for (int ni = 0; ni < 2; ni++)
                    mma8(acc[mi][ni], af[mi], bf[ni]);
        }
    }
    __syncthreads();

    // epilogue: divide by z, relu, store
    #pragma unroll
    for (int mi = 0; mi < 4; mi++) {
        #pragma unroll
        for (int half = 0; half < 2; half++) {
            int row = i0 + mi * 16 + g + half * 8;
            if (row >= N) continue;
            float inv = 1.f / zrow[mi * 16 + g + half * 8];
            #pragma unroll
            for (int ni = 0; ni < 2; ni++) {
                int col = warp * 16 + ni * 8 + tg * 2;
                float v0 = acc[mi][ni][half * 2 + 0] * inv;
                float v1 = acc[mi][ni][half * 2 + 1] * inv;
                v0 = v0 > 0.f ? v0 : 0.f;
                v1 = v1 > 0.f ? v1 : 0.f;
                *(float2*)&out[(long)b * N * HH + (long)row * HH + col] = make_float2(v0, v1);
            }
        }
    }
}

// ---------------- small helper kernels ----------------
__global__ void scores_kernel(const float* __restrict__ h,
                              const float* __restrict__ a1,
                              const float* __restrict__ a2,
                              float* __restrict__ s1, float* __restrict__ s2, int N)
{
    int b = blockIdx.y;
    int warp = threadIdx.x >> 5, lane = threadIdx.x & 31;
    int row = blockIdx.x * 4 + warp;
    if (row >= N) return;
    const float* hr = h + ((long)b * N + row) * HH;
    float p1 = 0.f, p2 = 0.f;
    #pragma unroll
    for (int i = 0; i < 4; i++) {
        float hv = hr[lane + 32 * i];
        p1 += hv * a1[lane + 32 * i];
        p2 += hv * a2[lane + 32 * i];
    }
    #pragma unroll
    for (int off = 16; off; off >>= 1) {
        p1 += __shfl_xor_sync(0xffffffffu, p1, off);
        p2 += __shfl_xor_sync(0xffffffffu, p2, off);
    }
    if (lane == 0) {
        s1[(long)b * N + row] = p1;
        s2[(long)b * N + row] = p2;
    }
}

__global__ void smax_kernel(const float* __restrict__ s2, float* __restrict__ smax, int N)
{
    __shared__ float red[256];
    int b = blockIdx.x;
    float m = -1e30f;
    for (int i = threadIdx.x; i < N; i += 256) m = fmaxf(m, s2[(long)b * N + i]);
    red[threadIdx.x] = m;
    __syncthreads();
    for (int s = 128; s > 0; s >>= 1) {
        if (threadIdx.x < s) red[threadIdx.x] = fmaxf(red[threadIdx.x], red[threadIdx.x + s]);
        __syncthreads();
    }
    if (threadIdx.x == 0) smax[b] = red[0];
}

__global__ void colsum_kernel(const float* __restrict__ A, float* __restrict__ sums)
{
    int v = blockIdx.x * 256 + threadIdx.x;
    if (v >= NVV) return;
    int b = blockIdx.y, seg = blockIdx.z;
    const float* Ab = A + (long)b * NOO * NVV;
    int o0 = seg * 125;
    float s = 0.f;
    #pragma unroll 4
    for (int o = o0; o < o0 + 125; o++) s += Ab[(long)o * NVV + v];
    atomicAdd(&sums[b * NVV + v], s);
}

__global__ void rvfin_kernel(const float* __restrict__ sums, float* __restrict__ rv, int n)
{
    int i = blockIdx.x * 256 + threadIdx.x;
    if (i < n) rv[i] = 1.f / (sums[i] + EPSF);
}

__global__ void rowsum_kernel(const float* __restrict__ A, const float* __restrict__ rv,
                              float* __restrict__ to_)
{
    int warp = threadIdx.x >> 5, lane = threadIdx.x & 31;
    int o = blockIdx.x * 8 + warp;
    int b = blockIdx.y;
    if (o >= NOO) return;
    const float* Ar  = A + ((long)b * NOO + o) * NVV;
    const float* rvb = rv + b * NVV;
    float s = 0.f;
    for (int v = lane; v < NVV; v += 32) s += Ar[v] * rvb[v];
    #pragma unroll
    for (int off = 16; off; off >>= 1) s += __shfl_xor_sync(0xffffffffu, s, off);
    if (lane == 0) to_[b * NOO + o] = 1.f / (s + EPSF);
}

__global__ void scale_kernel(const float* __restrict__ x, const float* __restrict__ rv,
                             float* __restrict__ y, int n)
{
    int i = blockIdx.x * 256 + threadIdx.x;
    if (i < n) y[i] = x[i] * rv[i >> 7];
}

// ---------------- host orchestration ----------------
static void launch_gemm(bool transA, const float* A, const float* Bm, float* C,
                        const float* bias, const float* res, const float* rowscale,
                        int M, int N, int K, long sA, long sB, long sC, int relu, int G)
{
    dim3 grid((N + GBN - 1) / GBN, (M + GBM - 1) / GBM, G);
    if (transA)
        gemm_tc<true><<<grid, 256>>>(A, Bm, C, bias, res, rowscale, M, N, K, sA, sB, sC, relu);
    else
        gemm_tc<false><<<grid, 256>>>(A, Bm, C, bias, res, rowscale, M, N, K, sA, sB, sC, relu);
}

extern "C" void kernel_launch(void* const* d_in, const int* in_sizes, int n_in,
                              void* d_out, int out_size)
{
    const float* vis_memory = (const float*)d_in[0];
    const float* obj_memory = (const float*)d_in[1];
    const float* vis_adj    = (const float*)d_in[2];
    const float* obj_adj    = (const float*)d_in[3];
    const float* A_OV       = (const float*)d_in[4];
    const float* Wv1  = (const float*)d_in[5];
    const float* av1a = (const float*)d_in[6];
    const float* av1b = (const float*)d_in[7];
    const float* Wv2  = (const float*)d_in[8];
    const float* av2a = (const float*)d_in[9];
    const float* av2b = (const float*)d_in[10];
    const float* Wo1  = (const float*)d_in[11];
    const float* ao1a = (const float*)d_in[12];
    const float* ao1b = (const float*)d_in[13];
    const float* Wo2  = (const float*)d_in[14];
    const float* ao2a = (const float*)d_in[15];
    const float* ao2b = (const float*)d_in[16];
    const float* g2o_W1 = (const float*)d_in[17];
    const float* g2o_b1 = (const float*)d_in[18];
    const float* g2o_W2 = (const float*)d_in[19];
    const float* g2o_b2 = (const float*)d_in[20];
    const float* o2g_W1 = (const float*)d_in[21];
    const float* o2g_b1 = (const float*)d_in[22];
    const float* o2g_W2 = (const float*)d_in[23];
    const float* o2g_b2 = (const float*)d_in[24];
    const float* img_W = (const float*)d_in[25];
    const float* img_b = (const float*)d_in[26];
    const float* obj_W = (const float*)d_in[27];
    const float* obj_b = (const float*)d_in[28];

    float *p_hv, *p_ho, *p_v, *p_o, *p_cv, *p_co, *p_m1v, *p_m1o, *p_vs, *p_vis, *p_obj;
    float *p_s1v, *p_s2v, *p_s1o, *p_s2o, *p_smaxv, *p_smaxo, *p_rvsum, *p_rv, *p_to;
    cudaGetSymbolAddress((void**)&p_hv,  g_hv);
    cudaGetSymbolAddress((void**)&p_ho,  g_ho);
    cudaGetSymbolAddress((void**)&p_v,   g_v);
    cudaGetSymbolAddress((void**)&p_o,   g_o);
    cudaGetSymbolAddress((void**)&p_cv,  g_cv);
    cudaGetSymbolAddress((void**)&p_co,  g_co);
    cudaGetSymbolAddress((void**)&p_m1v, g_m1v);
    cudaGetSymbolAddress((void**)&p_m1o, g_m1o);
    cudaGetSymbolAddress((void**)&p_vs,  g_vs);
    cudaGetSymbolAddress((void**)&p_vis, g_vis);
    cudaGetSymbolAddress((void**)&p_obj, g_obj);
    cudaGetSymbolAddress((void**)&p_s1v, g_s1v);
    cudaGetSymbolAddress((void**)&p_s2v, g_s2v);
    cudaGetSymbolAddress((void**)&p_s1o, g_s1o);
    cudaGetSymbolAddress((void**)&p_s2o, g_s2o);
    cudaGetSymbolAddress((void**)&p_smaxv, g_smaxv);
    cudaGetSymbolAddress((void**)&p_smaxo, g_smaxo);
    cudaGetSymbolAddress((void**)&p_rvsum, g_rvsum);
    cudaGetSymbolAddress((void**)&p_rv,  g_rv);
    cudaGetSymbolAddress((void**)&p_to,  g_to);

    cudaFuncSetAttribute(attn_tc, cudaFuncAttributeMaxDynamicSharedMemorySize, ATTN_SMEM_TC);

    // cross-adjacency normalizers
    cudaMemsetAsync(p_rvsum, 0, BB * NVV * sizeof(float));
    colsum_kernel<<<dim3(2, BB, 12), 256>>>(A_OV, p_rvsum);
    rvfin_kernel<<<(BB * NVV + 255) / 256, 256>>>(p_rvsum, p_rv, BB * NVV);
    rowsum_kernel<<<dim3((NOO + 7) / 8, BB), 256>>>(A_OV, p_rv, p_to);

    for (int round = 0; round < 2; round++) {
        const float* xv  = (round == 0) ? vis_memory : p_vis;
        const float* xo  = (round == 0) ? obj_memory : p_obj;
        int Kv           = (round == 0) ? DVV : HH;
        int Ko           = (round == 0) ? DOO : HH;
        const float* Wv  = (round == 0) ? Wv1  : Wv2;
        const float* ava = (round == 0) ? av1a : av2a;
        const float* avb = (round == 0) ? av1b : av2b;
        const float* Wo  = (round == 0) ? Wo1  : Wo2;
        const float* aoa = (round == 0) ? ao1a : ao2a;
        const float* aob = (round == 0) ? ao1b : ao2b;

        // h = x @ W   (flattened over batch)
        launch_gemm(false, xv, Wv, p_hv, nullptr, nullptr, nullptr,
                    BB * NVV, HH, Kv, 0, 0, 0, 0, 1);
        launch_gemm(false, xo, Wo, p_ho, nullptr, nullptr, nullptr,
                    BB * NOO, HH, Ko, 0, 0, 0, 0, 1);

        // attention scores + per-batch max
        scores_kernel<<<dim3((NVV + 3) / 4, BB), 128>>>(p_hv, ava, avb, p_s1v, p_s2v, NVV);
        scores_kernel<<<dim3((NOO + 3) / 4, BB), 128>>>(p_ho, aoa, aob, p_s1o, p_s2o, NOO);
        smax_kernel<<<BB, 256>>>(p_s2v, p_smaxv, NVV);
        smax_kernel<<<BB, 256>>>(p_s2o, p_smaxo, NOO);

        // fused masked softmax @ h + relu (tensor core)
        attn_tc<<<dim3((NVV + AROWS - 1) / AROWS, BB), 256, ATTN_SMEM_TC>>>(
            p_hv, vis_adj, p_s1v, p_s2v, p_smaxv, p_v, NVV);
        attn_tc<<<dim3((NOO + AROWS - 1) / AROWS, BB), 256, ATTN_SMEM_TC>>>(
            p_ho, obj_adj, p_s1o, p_s2o, p_smaxo, p_o, NOO);

        // cv = rv ⊙ (A^T @ o)
        launch_gemm(true, A_OV, p_o, p_cv, nullptr, nullptr, p_rv,
                    NVV, HH, NOO, (long)NOO * NVV, (long)NOO * HH, (long)NVV * HH, 0, BB);
        // vis = v + mlp(cv; o2g)  (flattened)
        launch_gemm(false, p_cv, o2g_W1, p_m1v, o2g_b1, nullptr, nullptr,
                    BB * NVV, HH, HH, 0, 0, 0, 1, 1);
        launch_gemm(false, p_m1v, o2g_W2, p_vis, o2g_b2, p_v, nullptr,
                    BB * NVV, HH, HH, 0, 0, 0, 0, 1);

        // co = to ⊙ (A @ (rv ⊙ v))
        scale_kernel<<<(BB * NVV * HH + 255) / 256, 256>>>(p_v, p_rv, p_vs, BB * NVV * HH);
        launch_gemm(false, A_OV, p_vs, p_co, nullptr, nullptr, p_to,
                    NOO, HH, NVV, (long)NOO * NVV, (long)NVV * HH, (long)NOO * HH, 0, BB);
        // obj = o + mlp(co; g2o)  (flattened)
        launch_gemm(false, p_co, g2o_W1, p_m1o, g2o_b1, nullptr, nullptr,
                    BB * NOO, HH, HH, 0, 0, 0, 1, 1);
        launch_gemm(false, p_m1o, g2o_W2, p_obj, g2o_b2, p_o, nullptr,
                    BB * NOO, HH, HH, 0, 0, 0, 0, 1);
    }

    // output projections (flattened)
    float* out_vis = (float*)d_out;
    float* out_obj = out_vis + (long)BB * NVV * DVV;
    launch_gemm(false, p_vis, img_W, out_vis, img_b, nullptr, nullptr,
                BB * NVV, DVV, HH, 0, 0, 0, 0, 1);
    launch_gemm(false, p_obj, obj_W, out_obj, obj_b, nullptr, nullptr,
                BB * NOO, DOO, HH, 0, 0, 0, 0, 1);
}

// round 3
// speedup vs baseline: 1.1547x; 1.0072x over previous
#include <cuda_runtime.h>
#include <math.h>

#define BB 8
#define NVV 500
#define NOO 1500
#define DVV 512
#define DOO 32
#define HH 128
#define EPSF 1e-5f

// ---------------- scratch ----------------
__device__ float g_hv [BB*NVV*HH];
__device__ float g_ho [BB*NOO*HH];
__device__ float g_v  [BB*NVV*HH];
__device__ float g_o  [BB*NOO*HH];
__device__ float g_cv [BB*NVV*HH];
__device__ float g_co [BB*NOO*HH];
__device__ float g_m1v[BB*NVV*HH];
__device__ float g_m1o[BB*NOO*HH];
__device__ float g_vs [BB*NVV*HH];
__device__ float g_vis[BB*NVV*HH];
__device__ float g_obj[BB*NOO*HH];
__device__ float g_s1v[BB*NVV];
__device__ float g_s2v[BB*NVV];
__device__ float g_s1o[BB*NOO];
__device__ float g_s2o[BB*NOO];
__device__ float g_smaxv[BB];
__device__ float g_smaxo[BB];
__device__ float g_rvsum[BB*NVV];
__device__ float g_rv  [BB*NVV];
__device__ float g_to  [BB*NOO];

// ---------------- tf32 mma helpers ----------------
__device__ __forceinline__ unsigned cvt_tf32(float x) {
    unsigned r; asm("cvt.rna.tf32.f32 %0, %1;" : "=r"(r) : "f"(x)); return r;
}
__device__ __forceinline__ void mma8(float* d, const unsigned* a, const unsigned* b) {
    asm volatile("mma.sync.aligned.m16n8k8.row.col.f32.tf32.tf32.f32 "
                 "{%0,%1,%2,%3},{%4,%5,%6,%7},{%8,%9},{%0,%1,%2,%3};"
                 : "+f"(d[0]), "+f"(d[1]), "+f"(d[2]), "+f"(d[3])
                 : "r"(a[0]), "r"(a[1]), "r"(a[2]), "r"(a[3]), "r"(b[0]), "r"(b[1]));
}

// ---------------- tf32 tensor-core GEMM ----------------
// C[b,m,n] = act( rowscale[b,m]*sum_k Aop[b,m,k]*B[b,k,n] + bias[n] + res[b,m,n] )
// block tile 128x64, BK=16, 256 threads (8 warps: 4m x 2n), warp tile 32x32.
#define GBM 128
#define GBN 64
#define GBK 16
#define SAP 136   // As stride (== 8 mod 32 -> conflict-free frag loads)
#define SBP 72    // Bs stride (== 8 mod 32)

template<bool TRANSA>
__global__ void __launch_bounds__(256) gemm_tc(const float* __restrict__ A,
                                               const float* __restrict__ Bm,
                                               float* __restrict__ C,
                                               const float* __restrict__ bias,
                                               const float* __restrict__ res,
                                               const float* __restrict__ rowscale,
                                               int M, int N, int K,
                                               long sA, long sB, long sC, int relu)
{
    __shared__ unsigned As[GBK * SAP];
    __shared__ unsigned Bs[GBK * SBP];

    int b = blockIdx.z;
    const float* Ab = A  + (long)b * sA;
    const float* Bb = Bm + (long)b * sB;
    int m0 = blockIdx.y * GBM;
    int n0 = blockIdx.x * GBN;
    int t = threadIdx.x;
    int warp = t >> 5, lane = t & 31;
    int g = lane >> 2, tg = lane & 3;
    int wm = warp >> 1, wn = warp & 1;

    float acc[2][4][4];
    #pragma unroll
    for (int mi = 0; mi < 2; mi++)
        #pragma unroll
        for (int ni = 0; ni < 4; ni++)
            #pragma unroll
            for (int e = 0; e < 4; e++) acc[mi][ni][e] = 0.f;

    // tile-load thread mapping
    int am, ak;
    if (TRANSA) { ak = t >> 4; am = (t & 15) * 8; }   // A stored (K x M)
    else        { am = t >> 1; ak = (t & 1) * 8; }    // A stored (M x K)
    int bk = t >> 4, bn = (t & 15) * 4;

    float4 ra[2], rb;
    const float4 z4 = make_float4(0.f, 0.f, 0.f, 0.f);

    // prefetch tile 0
    {
        int k0 = 0;
        if (TRANSA) {
            bool kok = (k0 + ak) < K;
            long base = (long)(k0 + ak) * M;
            #pragma unroll
            for (int i = 0; i < 2; i++) {
                int gm = m0 + am + i * 4;
                ra[i] = (kok && gm < M) ? *(const float4*)&Ab[base + gm] : z4;
            }
        } else {
            int gm = m0 + am;
            #pragma unroll
            for (int i = 0; i < 2; i++) {
                int gk = k0 + ak + i * 4;
                ra[i] = (gm < M && gk < K) ? *(const float4*)&Ab[(long)gm * K + gk] : z4;
            }
        }
        int gk = k0 + bk, gn = n0 + bn;
        rb = (gk < K && gn < N) ? *(const float4*)&Bb[(long)gk * N + gn] : z4;
    }

    int ntiles = (K + GBK - 1) / GBK;
    for (int it = 0; it < ntiles; it++) {
        // store current tile to smem (with tf32 rounding)
        if (TRANSA) {
            #pragma unroll
            for (int i = 0; i < 2; i++) {
                uint4 u;
                u.x = cvt_tf32(ra[i].x); u.y = cvt_tf32(ra[i].y);
                u.z = cvt_tf32(ra[i].z); u.w = cvt_tf32(ra[i].w);
                *(uint4*)&As[ak * SAP + am + i * 4] = u;
            }
        } else {
            #pragma unroll
            for (int i = 0; i < 2; i++) {
                float v[4] = {ra[i].x, ra[i].y, ra[i].z, ra[i].w};
                #pragma unroll
                for (int e = 0; e < 4; e++)
                    As[(ak + i * 4 + e) * SAP + am] = cvt_tf32(v[e]);
            }
        }
        {
            uint4 u;
            u.x = cvt_tf32(rb.x); u.y = cvt_tf32(rb.y);
            u.z = cvt_tf32(rb.z); u.w = cvt_tf32(rb.w);
            *(uint4*)&Bs[bk * SBP + bn] = u;
        }
        __syncthreads();

        // prefetch next tile
        if (it + 1 < ntiles) {
            int k0 = (it + 1) * GBK;
            if (TRANSA) {
                bool kok = (k0 + ak) < K;
                long base = (long)(k0 + ak) * M;
                #pragma unroll
                for (int i = 0; i < 2; i++) {
                    int gm = m0 + am + i * 4;
                    ra[i] = (kok && gm < M) ? *(const float4*)&Ab[base + gm] : z4;
                }
            } else {
                int gm = m0 + am;
                #pragma unroll
                for (int i = 0; i < 2; i++) {
                    int gk = k0 + ak + i * 4;
                    ra[i] = (gm < M && gk < K) ? *(const float4*)&Ab[(long)gm * K + gk] : z4;
                }
            }
            int gk = k0 + bk, gn = n0 + bn;
            rb = (gk < K && gn < N) ? *(const float4*)&Bb[(long)gk * N + gn] : z4;
        }

        // compute
        #pragma unroll
        for (int kk = 0; kk < GBK; kk += 8) {
            unsigned af[2][4], bf[4][2];
            #pragma unroll
            for (int mi = 0; mi < 2; mi++) {
                int mb = wm * 32 + mi * 16 + g;
                af[mi][0] = As[(kk + tg) * SAP + mb];
                af[mi][1] = As[(kk + tg) * SAP + mb + 8];
                af[mi][2] = As[(kk + tg + 4) * SAP + mb];
                af[mi][3] = As[(kk + tg + 4) * SAP + mb + 8];
            }
            #pragma unroll
            for (int ni = 0; ni < 4; ni++) {
                int nb = wn * 32 + ni * 8 + g;
                bf[ni][0] = Bs[(kk + tg) * SBP + nb];
                bf[ni][1] = Bs[(kk + tg + 4) * SBP + nb];
            }
            #pragma unroll
            for (int mi = 0; mi < 2; mi++)
                #pragma unroll
                for (int ni = 0; ni < 4; ni++)
                    mma8(acc[mi][ni], af[mi], bf[ni]);
        }
        __syncthreads();
    }

    // epilogue
    #pragma unroll
    for (int mi = 0; mi < 2; mi++) {
        #pragma unroll
        for (int half = 0; half < 2; half++) {
            int row = m0 + wm * 32 + mi * 16 + g + half * 8;
            if (row >= M) continue;
            float scale = rowscale ? rowscale[b * M + row] : 1.f;
            #pragma unroll
            for (int ni = 0; ni < 4; ni++) {
                int col = n0 + wn * 32 + ni * 8 + tg * 2;
                if (col >= N) continue;
                float v0 = acc[mi][ni][half * 2 + 0] * scale;
                float v1 = acc[mi][ni][half * 2 + 1] * scale;
                if (bias) { v0 += bias[col]; v1 += bias[col + 1]; }
                long off = (long)b * sC + (long)row * N + col;
                if (res) { v0 += res[off]; v1 += res[off + 1]; }
                if (relu) { v0 = v0 > 0.f ? v0 : 0.f; v1 = v1 > 0.f ? v1 : 0.f; }
                *(float2*)&C[off] = make_float2(v0, v1);
            }
        }
    }
}

// ---------------- fused masked-softmax attention with tf32 mma ----------------
// out = relu( softmax(mask(lrelu(s1_i + s2_j))) @ h ), single pass using global
// max of s2 as a safe row-max. 64 rows x 128 feats per block, 128-j chunks.
#define AROWS 64
#define AJC 128
#define HS_S 136
#define WS_S 132
#define ATTN_SMEM_TC ((128*HS_S + AROWS*WS_S + AROWS) * 4)

__global__ void __launch_bounds__(256) attn_tc(const float* __restrict__ hbuf,
                                               const float* __restrict__ adj,
                                               const float* __restrict__ s1,
                                               const float* __restrict__ s2,
                                               const float* __restrict__ smax,
                                               float* __restrict__ out,
                                               int N)
{
    extern __shared__ unsigned smu[];
    unsigned* hs = smu;                       // [128][HS_S] tf32 of h chunk (j, f)
    unsigned* ws = smu + 128 * HS_S;          // [AROWS][WS_S] tf32 weights (r, j)
    float* zrow  = (float*)(ws + AROWS * WS_S);

    int b = blockIdx.y;
    int i0 = blockIdx.x * AROWS;
    int t = threadIdx.x;
    int warp = t >> 5, lane = t & 31;
    int g = lane >> 2, tg = lane & 3;

    const float* hb   = hbuf + (long)b * N * HH;
    const float* adjb = adj  + (long)b * N * N;
    const float* s2b  = s2   + (long)b * N;

    float acc[4][2][4];
    #pragma unroll
    for (int mi = 0; mi < 4; mi++)
        #pragma unroll
        for (int ni = 0; ni < 2; ni++)
            #pragma unroll
            for (int e = 0; e < 4; e++) acc[mi][ni][e] = 0.f;

    if (t < AROWS) zrow[t] = 0.f;

    // weight-producer role: 4 threads per row, 32 j's each
    int pr = t >> 2;
    int pj = (t & 3) * 32;
    int prow = i0 + pr;
    float s1r = 0.f, mrow = 0.f;
    if (prow < N) {
        s1r = s1[(long)b * N + prow];
        float x = s1r + smax[b];
        mrow = x > 0.f ? x : 0.2f * x;
    }

    // h stage role: warp-row + q*8, 4 floats per lane
    int hrow0 = t >> 5;
    int hf4 = (t & 31) * 4;

    for (int j0 = 0; j0 < N; j0 += AJC) {
        __syncthreads();   // smem free from previous chunk's mma reads

        // stage h chunk (coalesced LDG.128, conflict-free STS.128)
        #pragma unroll
        for (int q = 0; q < 16; q++) {
            int jj = hrow0 + q * 8;
            int gj = j0 + jj;
            uint4 u;
            if (gj < N) {
                float4 v = *(const float4*)&hb[(long)gj * HH + hf4];
                u.x = cvt_tf32(v.x); u.y = cvt_tf32(v.y);
                u.z = cvt_tf32(v.z); u.w = cvt_tf32(v.w);
            } else {
                u = make_uint4(0, 0, 0, 0);
            }
            *(uint4*)&hs[jj * HS_S + hf4] = u;
        }

        // compute weight tile + partial row sums
        float zl = 0.f;
        if (prow < N) {
            const float* arow = adjb + (long)prow * N + j0;
            #pragma unroll 8
            for (int q = 0; q < 32; q++) {
                int j = pj + q;
                int gj = j0 + j;
                float w = 0.f;
                if (gj < N) {
                    float a = arow[j];
                    if (a > 0.f) {
                        float x = s1r + s2b[gj];
                        float e = x > 0.f ? x : 0.2f * x;
                        w = __expf(e - mrow);
                    }
                }
                unsigned wu = cvt_tf32(w);
                ws[pr * WS_S + j] = wu;
                zl += __uint_as_float(wu);
            }
        } else {
            #pragma unroll 8
            for (int q = 0; q < 32; q++) ws[pr * WS_S + pj + q] = 0u;
        }
        zl += __shfl_down_sync(0xffffffffu, zl, 2);
        zl += __shfl_down_sync(0xffffffffu, zl, 1);
        if ((t & 3) == 0 && prow < N) zrow[pr] += zl;
        __syncthreads();

        // acc += ws(64x128) @ hs(128x128): m16n8k8 tf32
        #pragma unroll
        for (int kk = 0; kk < AJC; kk += 8) {
            unsigned af[4][4], bf[2][2];
            #pragma unroll
            for (int mi = 0; mi < 4; mi++) {
                int mb = mi * 16 + g;
                af[mi][0] = ws[mb * WS_S + kk + tg];
                af[mi][1] = ws[(mb + 8) * WS_S + kk + tg];
                af[mi][2] = ws[mb * WS_S + kk + tg + 4];
                af[mi][3] = ws[(mb + 8) * WS_S + kk + tg + 4];
            }
            #pragma unroll
            for (int ni = 0; ni < 2; ni++) {
                int nb = warp * 16 + ni * 8 + g;
                bf[ni][0] = hs[(kk + tg) * HS_S + nb];
                bf[ni][1] = hs[(kk + tg + 4) * HS_S + nb];
            }
            #pragma unroll
            for (int mi = 0; mi < 4; mi++)
                #pragma unroll
                for (int ni = 0; ni < 2; ni++)
                    mma8(acc[mi][ni], af[mi], bf[ni]);
        }
    }
    __syncthreads();

    // epilogue: divide by z, relu, store
    #pragma unroll
    for (int mi = 0; mi < 4; mi++) {
        #pragma unroll
        for (int half = 0; half < 2; half++) {
            int row = i0 + mi * 16 + g + half * 8;
            if (row >= N) continue;
            float inv = 1.f / zrow[mi * 16 + g + half * 8];
            #pragma unroll
            for (int ni = 0; ni < 2; ni++) {
                int col = warp * 16 + ni * 8 + tg * 2;
                float v0 = acc[mi][ni][half * 2 + 0] * inv;
                float v1 = acc[mi][ni][half * 2 + 1] * inv;
                v0 = v0 > 0.f ? v0 : 0.f;
                v1 = v1 > 0.f ? v1 : 0.f;
                *(float2*)&out[(long)b * N * HH + (long)row * HH + col] = make_float2(v0, v1);
            }
        }
    }
}

// ---------------- small helper kernels ----------------
__global__ void scores_kernel(const float* __restrict__ h,
                              const float* __restrict__ a1,
                              const float* __restrict__ a2,
                              float* __restrict__ s1, float* __restrict__ s2, int N)
{
    int b = blockIdx.y;
    int warp = threadIdx.x >> 5, lane = threadIdx.x & 31;
    int row = blockIdx.x * 4 + warp;
    if (row >= N) return;
    const float* hr = h + ((long)b * N + row) * HH;
    float p1 = 0.f, p2 = 0.f;
    #pragma unroll
    for (int i = 0; i < 4; i++) {
        float hv = hr[lane + 32 * i];
        p1 += hv * a1[lane + 32 * i];
        p2 += hv * a2[lane + 32 * i];
    }
    #pragma unroll
    for (int off = 16; off; off >>= 1) {
        p1 += __shfl_xor_sync(0xffffffffu, p1, off);
        p2 += __shfl_xor_sync(0xffffffffu, p2, off);
    }
    if (lane == 0) {
        s1[(long)b * N + row] = p1;
        s2[(long)b * N + row] = p2;
    }
}

__global__ void smax_kernel(const float* __restrict__ s2, float* __restrict__ smax, int N)
{
    __shared__ float red[256];
    int b = blockIdx.x;
    float m = -1e30f;
    for (int i = threadIdx.x; i < N; i += 256) m = fmaxf(m, s2[(long)b * N + i]);
    red[threadIdx.x] = m;
    __syncthreads();
    for (int s = 128; s > 0; s >>= 1) {
        if (threadIdx.x < s) red[threadIdx.x] = fmaxf(red[threadIdx.x], red[threadIdx.x + s]);
        __syncthreads();
    }
    if (threadIdx.x == 0) smax[b] = red[0];
}

__global__ void colsum_kernel(const float* __restrict__ A, float* __restrict__ sums)
{
    int v = blockIdx.x * 256 + threadIdx.x;
    if (v >= NVV) return;
    int b = blockIdx.y, seg = blockIdx.z;
    const float* Ab = A + (long)b * NOO * NVV;
    int o0 = seg * 125;
    float s = 0.f;
    #pragma unroll 4
    for (int o = o0; o < o0 + 125; o++) s += Ab[(long)o * NVV + v];
    atomicAdd(&sums[b * NVV + v], s);
}

__global__ void rvfin_kernel(const float* __restrict__ sums, float* __restrict__ rv, int n)
{
    int i = blockIdx.x * 256 + threadIdx.x;
    if (i < n) rv[i] = 1.f / (sums[i] + EPSF);
}

__global__ void rowsum_kernel(const float* __restrict__ A, const float* __restrict__ rv,
                              float* __restrict__ to_)
{
    int warp = threadIdx.x >> 5, lane = threadIdx.x & 31;
    int o = blockIdx.x * 8 + warp;
    int b = blockIdx.y;
    if (o >= NOO) return;
    const float* Ar  = A + ((long)b * NOO + o) * NVV;
    const float* rvb = rv + b * NVV;
    float s = 0.f;
    for (int v = lane; v < NVV; v += 32) s += Ar[v] * rvb[v];
    #pragma unroll
    for (int off = 16; off; off >>= 1) s += __shfl_xor_sync(0xffffffffu, s, off);
    if (lane == 0) to_[b * NOO + o] = 1.f / (s + EPSF);
}

__global__ void scale_kernel(const float* __restrict__ x, const float* __restrict__ rv,
                             float* __restrict__ y, int n)
{
    int i = blockIdx.x * 256 + threadIdx.x;
    if (i < n) y[i] = x[i] * rv[i >> 7];
}

// ---------------- host orchestration ----------------
static void launch_gemm(bool transA, const float* A, const float* Bm, float* C,
                        const float* bias, const float* res, const float* rowscale,
                        int M, int N, int K, long sA, long sB, long sC, int relu, int G)
{
    dim3 grid((N + GBN - 1) / GBN, (M + GBM - 1) / GBM, G);
    if (transA)
        gemm_tc<true><<<grid, 256>>>(A, Bm, C, bias, res, rowscale, M, N, K, sA, sB, sC, relu);
    else
        gemm_tc<false><<<grid, 256>>>(A, Bm, C, bias, res, rowscale, M, N, K, sA, sB, sC, relu);
}

extern "C" void kernel_launch(void* const* d_in, const int* in_sizes, int n_in,
                              void* d_out, int out_size)
{
    const float* vis_memory = (const float*)d_in[0];
    const float* obj_memory = (const float*)d_in[1];
    const float* vis_adj    = (const float*)d_in[2];
    const float* obj_adj    = (const float*)d_in[3];
    const float* A_OV       = (const float*)d_in[4];
    const float* Wv1  = (const float*)d_in[5];
    const float* av1a = (const float*)d_in[6];
    const float* av1b = (const float*)d_in[7];
    const float* Wv2  = (const float*)d_in[8];
    const float* av2a = (const float*)d_in[9];
    const float* av2b = (const float*)d_in[10];
    const float* Wo1  = (const float*)d_in[11];
    const float* ao1a = (const float*)d_in[12];
    const float* ao1b = (const float*)d_in[13];
    const float* Wo2  = (const float*)d_in[14];
    const float* ao2a = (const float*)d_in[15];
    const float* ao2b = (const float*)d_in[16];
    const float* g2o_W1 = (const float*)d_in[17];
    const float* g2o_b1 = (const float*)d_in[18];
    const float* g2o_W2 = (const float*)d_in[19];
    const float* g2o_b2 = (const float*)d_in[20];
    const float* o2g_W1 = (const float*)d_in[21];
    const float* o2g_b1 = (const float*)d_in[22];
    const float* o2g_W2 = (const float*)d_in[23];
    const float* o2g_b2 = (const float*)d_in[24];
    const float* img_W = (const float*)d_in[25];
    const float* img_b = (const float*)d_in[26];
    const float* obj_W = (const float*)d_in[27];
    const float* obj_b = (const float*)d_in[28];

    float *p_hv, *p_ho, *p_v, *p_o, *p_cv, *p_co, *p_m1v, *p_m1o, *p_vs, *p_vis, *p_obj;
    float *p_s1v, *p_s2v, *p_s1o, *p_s2o, *p_smaxv, *p_smaxo, *p_rvsum, *p_rv, *p_to;
    cudaGetSymbolAddress((void**)&p_hv,  g_hv);
    cudaGetSymbolAddress((void**)&p_ho,  g_ho);
    cudaGetSymbolAddress((void**)&p_v,   g_v);
    cudaGetSymbolAddress((void**)&p_o,   g_o);
    cudaGetSymbolAddress((void**)&p_cv,  g_cv);
    cudaGetSymbolAddress((void**)&p_co,  g_co);
    cudaGetSymbolAddress((void**)&p_m1v, g_m1v);
    cudaGetSymbolAddress((void**)&p_m1o, g_m1o);
    cudaGetSymbolAddress((void**)&p_vs,  g_vs);
    cudaGetSymbolAddress((void**)&p_vis, g_vis);
    cudaGetSymbolAddress((void**)&p_obj, g_obj);
    cudaGetSymbolAddress((void**)&p_s1v, g_s1v);
    cudaGetSymbolAddress((void**)&p_s2v, g_s2v);
    cudaGetSymbolAddress((void**)&p_s1o, g_s1o);
    cudaGetSymbolAddress((void**)&p_s2o, g_s2o);
    cudaGetSymbolAddress((void**)&p_smaxv, g_smaxv);
    cudaGetSymbolAddress((void**)&p_smaxo, g_smaxo);
    cudaGetSymbolAddress((void**)&p_rvsum, g_rvsum);
    cudaGetSymbolAddress((void**)&p_rv,  g_rv);
    cudaGetSymbolAddress((void**)&p_to,  g_to);

    cudaFuncSetAttribute(attn_tc, cudaFuncAttributeMaxDynamicSharedMemorySize, ATTN_SMEM_TC);

    // cross-adjacency normalizers
    cudaMemsetAsync(p_rvsum, 0, BB * NVV * sizeof(float));
    colsum_kernel<<<dim3(2, BB, 12), 256>>>(A_OV, p_rvsum);
    rvfin_kernel<<<(BB * NVV + 255) / 256, 256>>>(p_rvsum, p_rv, BB * NVV);
    rowsum_kernel<<<dim3((NOO + 7) / 8, BB), 256>>>(A_OV, p_rv, p_to);

    for (int round = 0; round < 2; round++) {
        const float* xv  = (round == 0) ? vis_memory : p_vis;
        const float* xo  = (round == 0) ? obj_memory : p_obj;
        int Kv           = (round == 0) ? DVV : HH;
        int Ko           = (round == 0) ? DOO : HH;
        const float* Wv  = (round == 0) ? Wv1  : Wv2;
        const float* ava = (round == 0) ? av1a : av2a;
        const float* avb = (round == 0) ? av1b : av2b;
        const float* Wo  = (round == 0) ? Wo1  : Wo2;
        const float* aoa = (round == 0) ? ao1a : ao2a;
        const float* aob = (round == 0) ? ao1b : ao2b;

        // h = x @ W   (flattened over batch)
        launch_gemm(false, xv, Wv, p_hv, nullptr, nullptr, nullptr,
                    BB * NVV, HH, Kv, 0, 0, 0, 0, 1);
        launch_gemm(false, xo, Wo, p_ho, nullptr, nullptr, nullptr,
                    BB * NOO, HH, Ko, 0, 0, 0, 0, 1);

        // attention scores + per-batch max
        scores_kernel<<<dim3((NVV + 3) / 4, BB), 128>>>(p_hv, ava, avb, p_s1v, p_s2v, NVV);
        scores_kernel<<<dim3((NOO + 3) / 4, BB), 128>>>(p_ho, aoa, aob, p_s1o, p_s2o, NOO);
        smax_kernel<<<BB, 256>>>(p_s2v, p_smaxv, NVV);
        smax_kernel<<<BB, 256>>>(p_s2o, p_smaxo, NOO);

        // fused masked softmax @ h + relu (tensor core)
        attn_tc<<<dim3((NVV + AROWS - 1) / AROWS, BB), 256, ATTN_SMEM_TC>>>(
            p_hv, vis_adj, p_s1v, p_s2v, p_smaxv, p_v, NVV);
        attn_tc<<<dim3((NOO + AROWS - 1) / AROWS, BB), 256, ATTN_SMEM_TC>>>(
            p_ho, obj_adj, p_s1o, p_s2o, p_smaxo, p_o, NOO);

        // cv = rv ⊙ (A^T @ o)
        launch_gemm(true, A_OV, p_o, p_cv, nullptr, nullptr, p_rv,
                    NVV, HH, NOO, (long)NOO * NVV, (long)NOO * HH, (long)NVV * HH, 0, BB);
        // vis = v + mlp(cv; o2g)  (flattened)
        launch_gemm(false, p_cv, o2g_W1, p_m1v, o2g_b1, nullptr, nullptr,
                    BB * NVV, HH, HH, 0, 0, 0, 1, 1);
        launch_gemm(false, p_m1v, o2g_W2, p_vis, o2g_b2, p_v, nullptr,
                    BB * NVV, HH, HH, 0, 0, 0, 0, 1);

        // co = to ⊙ (A @ (rv ⊙ v))
        scale_kernel<<<(BB * NVV * HH + 255) / 256, 256>>>(p_v, p_rv, p_vs, BB * NVV * HH);
        launch_gemm(false, A_OV, p_vs, p_co, nullptr, nullptr, p_to,
                    NOO, HH, NVV, (long)NOO * NVV, (long)NVV * HH, (long)NOO * HH, 0, BB);
        // obj = o + mlp(co; g2o)  (flattened)
        launch_gemm(false, p_co, g2o_W1, p_m1o, g2o_b1, nullptr, nullptr,
                    BB * NOO, HH, HH, 0, 0, 0, 1, 1);
        launch_gemm(false, p_m1o, g2o_W2, p_obj, g2o_b2, p_o, nullptr,
                    BB * NOO, HH, HH, 0, 0, 0, 0, 1);
    }

    // output projections (flattened)
    float* out_vis = (float*)d_out;
    float* out_obj = out_vis + (long)BB * NVV * DVV;
    launch_gemm(false, p_vis, img_W, out_vis, img_b, nullptr, nullptr,
                BB * NVV, DVV, HH, 0, 0, 0, 0, 1);
    launch_gemm(false, p_obj, obj_W, out_obj, obj_b, nullptr, nullptr,
                BB * NOO, DOO, HH, 0, 0, 0, 0, 1);
}

// round 4
// speedup vs baseline: 2.4716x; 2.1404x over previous
#include <cuda_runtime.h>
#include <math.h>

#define BB 8
#define NVV 500
#define NOO 1500
#define DVV 512
#define DOO 32
#define HH 128
#define EPSF 1e-5f

// ---------------- scratch ----------------
__device__ float g_hv [BB*NVV*HH];
__device__ float g_ho [BB*NOO*HH];
__device__ float g_v  [BB*NVV*HH];
__device__ float g_o  [BB*NOO*HH];
__device__ float g_cv [BB*NVV*HH];
__device__ float g_co [BB*NOO*HH];
__device__ float g_m1v[BB*NVV*HH];
__device__ float g_m1o[BB*NOO*HH];
__device__ float g_vis[BB*NVV*HH];
__device__ float g_obj[BB*NOO*HH];
__device__ float g_s1v[BB*NVV];
__device__ float g_s2v[BB*NVV];
__device__ float g_s1o[BB*NOO];
__device__ float g_s2o[BB*NOO];
__device__ float g_smaxv[BB];
__device__ float g_smaxo[BB];
__device__ float g_rvsum[BB*NVV];
__device__ float g_rv  [BB*NVV];
__device__ float g_to  [BB*NOO];

// ---------------- tf32 mma helpers ----------------
__device__ __forceinline__ unsigned cvt_tf32(float x) {
    unsigned r; asm("cvt.rna.tf32.f32 %0, %1;" : "=r"(r) : "f"(x)); return r;
}
__device__ __forceinline__ void mma8(float* d, const unsigned* a, const unsigned* b) {
    asm volatile("mma.sync.aligned.m16n8k8.row.col.f32.tf32.tf32.f32 "
                 "{%0,%1,%2,%3},{%4,%5,%6,%7},{%8,%9},{%0,%1,%2,%3};"
                 : "+f"(d[0]), "+f"(d[1]), "+f"(d[2]), "+f"(d[3])
                 : "r"(a[0]), "r"(a[1]), "r"(a[2]), "r"(a[3]), "r"(b[0]), "r"(b[1]));
}

// ---------------- dual-job tf32 GEMM: 64x64 tile, 128 threads ----------------
// C[b,m,n] = act( rowscale[b,m]*sum_k Aop[b,m,k]*(kscale[b,k]*B[b,k,n]) + bias[n] + res[b,m,n] )
#define TBM 64
#define TBN 64
#define TBK 16
#define TS 72   // smem row stride (==8 mod 32 -> conflict-free frags)

struct GJob {
    const float* A; const float* Bm; float* C;
    const float* bias; const float* res; const float* rowscale; const float* kscale;
    int M, N, K; long sA, sB, sC;
    int relu, transA, gx, gy, total;   // total = gx*gy*gz
};

__global__ void __launch_bounds__(128) gemm_tc2(GJob j0, GJob j1)
{
    __shared__ unsigned As[TBK * TS];
    __shared__ unsigned Bs[TBK * TS];

    GJob j; int bid;
    if (blockIdx.x < (unsigned)j0.total) { j = j0; bid = blockIdx.x; }
    else                                 { j = j1; bid = blockIdx.x - j0.total; }

    int per = j.gx * j.gy;
    int b   = bid / per;
    int rem = bid - b * per;
    int by  = rem / j.gx;
    int bx  = rem - by * j.gx;

    const float* Ab = j.A  + (long)b * j.sA;
    const float* Bb = j.Bm + (long)b * j.sB;
    int m0 = by * TBM, n0 = bx * TBN;
    int M = j.M, N = j.N, K = j.K;

    int t = threadIdx.x;
    int warp = t >> 5, lane = t & 31;
    int g = lane >> 2, tg = lane & 3;
    int wm = warp >> 1, wn = warp & 1;

    float acc[2][4][4];
    #pragma unroll
    for (int mi = 0; mi < 2; mi++)
        #pragma unroll
        for (int ni = 0; ni < 4; ni++)
            #pragma unroll
            for (int e = 0; e < 4; e++) acc[mi][ni][e] = 0.f;

    // load thread mappings
    int am = t >> 1,  ak = (t & 1) * 8;        // non-trans A (M x K)
    int akT = t >> 3, amT = (t & 7) * 8;       // trans A (K x M)
    int bk = t >> 3,  bn = (t & 7) * 8;        // B (K x N)

    const float4 z4 = make_float4(0.f, 0.f, 0.f, 0.f);
    float4 ra[2], rb[2];
    float ksv = 1.f;

    // prefetch tile 0
    {
        int k0 = 0;
        if (j.transA) {
            bool kok = (k0 + akT) < K;
            long base = (long)(k0 + akT) * M;
            #pragma unroll
            for (int i = 0; i < 2; i++) {
                int gm = m0 + amT + i * 4;
                ra[i] = (kok && gm < M) ? *(const float4*)&Ab[base + gm] : z4;
            }
        } else {
            int gm = m0 + am;
            #pragma unroll
            for (int i = 0; i < 2; i++) {
                int gk = k0 + ak + i * 4;
                ra[i] = (gm < M && gk < K) ? *(const float4*)&Ab[(long)gm * K + gk] : z4;
            }
        }
        int gk = k0 + bk;
        bool kok = gk < K;
        ksv = (j.kscale && kok) ? j.kscale[(long)b * K + gk] : 1.f;
        #pragma unroll
        for (int i = 0; i < 2; i++) {
            int gn = n0 + bn + i * 4;
            rb[i] = (kok && gn < N) ? *(const float4*)&Bb[(long)gk * N + gn] : z4;
        }
    }

    int ntiles = (K + TBK - 1) / TBK;
    for (int it = 0; it < ntiles; it++) {
        // store to smem with tf32 rounding
        if (j.transA) {
            #pragma unroll
            for (int i = 0; i < 2; i++) {
                uint4 u;
                u.x = cvt_tf32(ra[i].x); u.y = cvt_tf32(ra[i].y);
                u.z = cvt_tf32(ra[i].z); u.w = cvt_tf32(ra[i].w);
                *(uint4*)&As[akT * TS + amT + i * 4] = u;
            }
        } else {
            #pragma unroll
            for (int i = 0; i < 2; i++) {
                float v[4] = {ra[i].x, ra[i].y, ra[i].z, ra[i].w};
                #pragma unroll
                for (int e = 0; e < 4; e++)
                    As[(ak + i * 4 + e) * TS + am] = cvt_tf32(v[e]);
            }
        }
        #pragma unroll
        for (int i = 0; i < 2; i++) {
            uint4 u;
            u.x = cvt_tf32(rb[i].x * ksv); u.y = cvt_tf32(rb[i].y * ksv);
            u.z = cvt_tf32(rb[i].z * ksv); u.w = cvt_tf32(rb[i].w * ksv);
            *(uint4*)&Bs[bk * TS + bn + i * 4] = u;
        }
        __syncthreads();

        // prefetch next tile
        if (it + 1 < ntiles) {
            int k0 = (it + 1) * TBK;
            if (j.transA) {
                bool kok = (k0 + akT) < K;
                long base = (long)(k0 + akT) * M;
                #pragma unroll
                for (int i = 0; i < 2; i++) {
                    int gm = m0 + amT + i * 4;
                    ra[i] = (kok && gm < M) ? *(const float4*)&Ab[base + gm] : z4;
                }
            } else {
                int gm = m0 + am;
                #pragma unroll
                for (int i = 0; i < 2; i++) {
                    int gk = k0 + ak + i * 4;
                    ra[i] = (gm < M && gk < K) ? *(const float4*)&Ab[(long)gm * K + gk] : z4;
                }
            }
            int gk = k0 + bk;
            bool kok = gk < K;
            ksv = (j.kscale && kok) ? j.kscale[(long)b * K + gk] : 1.f;
            #pragma unroll
            for (int i = 0; i < 2; i++) {
                int gn = n0 + bn + i * 4;
                rb[i] = (kok && gn < N) ? *(const float4*)&Bb[(long)gk * N + gn] : z4;
            }
        }

        // compute
        #pragma unroll
        for (int kk = 0; kk < TBK; kk += 8) {
            unsigned af[2][4], bf[4][2];
            #pragma unroll
            for (int mi = 0; mi < 2; mi++) {
                int mb = wm * 32 + mi * 16 + g;
                af[mi][0] = As[(kk + tg) * TS + mb];
                af[mi][1] = As[(kk + tg) * TS + mb + 8];
                af[mi][2] = As[(kk + tg + 4) * TS + mb];
                af[mi][3] = As[(kk + tg + 4) * TS + mb + 8];
            }
            #pragma unroll
            for (int ni = 0; ni < 4; ni++) {
                int nb = wn * 32 + ni * 8 + g;
                bf[ni][0] = Bs[(kk + tg) * TS + nb];
                bf[ni][1] = Bs[(kk + tg + 4) * TS + nb];
            }
            #pragma unroll
            for (int mi = 0; mi < 2; mi++)
                #pragma unroll
                for (int ni = 0; ni < 4; ni++)
                    mma8(acc[mi][ni], af[mi], bf[ni]);
        }
        __syncthreads();
    }

    // epilogue
    #pragma unroll
    for (int mi = 0; mi < 2; mi++) {
        #pragma unroll
        for (int half = 0; half < 2; half++) {
            int row = m0 + wm * 32 + mi * 16 + g + half * 8;
            if (row >= M) continue;
            float scale = j.rowscale ? j.rowscale[b * M + row] : 1.f;
            #pragma unroll
            for (int ni = 0; ni < 4; ni++) {
                int col = n0 + wn * 32 + ni * 8 + tg * 2;
                if (col >= N) continue;
                float v0 = acc[mi][ni][half * 2 + 0] * scale;
                float v1 = acc[mi][ni][half * 2 + 1] * scale;
                if (j.bias) { v0 += j.bias[col]; v1 += j.bias[col + 1]; }
                long off = (long)b * j.sC + (long)row * N + col;
                if (j.res) { v0 += j.res[off]; v1 += j.res[off + 1]; }
                if (j.relu) { v0 = v0 > 0.f ? v0 : 0.f; v1 = v1 > 0.f ? v1 : 0.f; }
                *(float2*)&j.C[off] = make_float2(v0, v1);
            }
        }
    }
}

// ---------------- dual-job fused masked-softmax attention ----------------
#define AROWS 64
#define AJC 128
#define HS_S 136
#define WS_S 132
#define ATTN_SMEM_TC ((128*HS_S + AROWS*WS_S + AROWS) * 4)

struct AJob {
    const float* h; const float* adj; const float* s1; const float* s2;
    const float* smax; float* out; int N; int nx; int total;
};

__global__ void __launch_bounds__(256) attn_tc2(AJob j0, AJob j1)
{
    extern __shared__ unsigned smu[];
    unsigned* hs = smu;                       // [128][HS_S]
    unsigned* ws = smu + 128 * HS_S;          // [AROWS][WS_S]
    float* zrow  = (float*)(ws + AROWS * WS_S);

    AJob j; int bid;
    if (blockIdx.x < (unsigned)j0.total) { j = j0; bid = blockIdx.x; }
    else                                 { j = j1; bid = blockIdx.x - j0.total; }
    int b  = bid / j.nx;
    int i0 = (bid - b * j.nx) * AROWS;
    int N  = j.N;

    int t = threadIdx.x;
    int warp = t >> 5, lane = t & 31;
    int g = lane >> 2, tg = lane & 3;

    const float* hb   = j.h   + (long)b * N * HH;
    const float* adjb = j.adj + (long)b * N * N;
    const float* s2b  = j.s2  + (long)b * N;

    float acc[4][2][4];
    #pragma unroll
    for (int mi = 0; mi < 4; mi++)
        #pragma unroll
        for (int ni = 0; ni < 2; ni++)
            #pragma unroll
            for (int e = 0; e < 4; e++) acc[mi][ni][e] = 0.f;

    if (t < AROWS) zrow[t] = 0.f;

    int pr = t >> 2;
    int pj = (t & 3) * 32;
    int prow = i0 + pr;
    float s1r = 0.f, mrow = 0.f;
    if (prow < N) {
        s1r = j.s1[(long)b * N + prow];
        float x = s1r + j.smax[b];
        mrow = x > 0.f ? x : 0.2f * x;
    }

    int hrow0 = t >> 5;
    int hf4 = (t & 31) * 4;

    for (int c0 = 0; c0 < N; c0 += AJC) {
        __syncthreads();

        // stage h chunk
        #pragma unroll
        for (int q = 0; q < 16; q++) {
            int jj = hrow0 + q * 8;
            int gj = c0 + jj;
            uint4 u;
            if (gj < N) {
                float4 v = *(const float4*)&hb[(long)gj * HH + hf4];
                u.x = cvt_tf32(v.x); u.y = cvt_tf32(v.y);
                u.z = cvt_tf32(v.z); u.w = cvt_tf32(v.w);
            } else {
                u = make_uint4(0, 0, 0, 0);
            }
            *(uint4*)&hs[jj * HS_S + hf4] = u;
        }

        // weight tile + partial z
        float zl = 0.f;
        if (prow < N) {
            const float* arow = adjb + (long)prow * N + c0;
            #pragma unroll
            for (int q4 = 0; q4 < 32; q4 += 4) {
                int jj = pj + q4;
                int gj = c0 + jj;
                float a[4], s[4];
                if (gj + 3 < N) {
                    float4 a4 = *(const float4*)&arow[jj];
                    float4 s4 = *(const float4*)&s2b[gj];
                    a[0]=a4.x; a[1]=a4.y; a[2]=a4.z; a[3]=a4.w;
                    s[0]=s4.x; s[1]=s4.y; s[2]=s4.z; s[3]=s4.w;
                } else {
                    #pragma unroll
                    for (int e = 0; e < 4; e++) {
                        bool ok = (gj + e) < N;
                        a[e] = ok ? arow[jj + e] : 0.f;
                        s[e] = ok ? s2b[gj + e] : 0.f;
                    }
                }
                #pragma unroll
                for (int e = 0; e < 4; e++) {
                    float w = 0.f;
                    if (a[e] > 0.f) {
                        float x = s1r + s[e];
                        float ev = x > 0.f ? x : 0.2f * x;
                        w = __expf(ev - mrow);
                    }
                    unsigned wu = cvt_tf32(w);
                    ws[pr * WS_S + jj + e] = wu;
                    zl += __uint_as_float(wu);
                }
            }
        } else {
            #pragma unroll 8
            for (int q = 0; q < 32; q++) ws[pr * WS_S + pj + q] = 0u;
        }
        zl += __shfl_down_sync(0xffffffffu, zl, 2);
        zl += __shfl_down_sync(0xffffffffu, zl, 1);
        if ((t & 3) == 0 && prow < N) zrow[pr] += zl;
        __syncthreads();

        // acc += ws(64x128) @ hs(128x128)
        #pragma unroll
        for (int kk = 0; kk < AJC; kk += 8) {
            unsigned af[4][4], bf[2][2];
            #pragma unroll
            for (int mi = 0; mi < 4; mi++) {
                int mb = mi * 16 + g;
                af[mi][0] = ws[mb * WS_S + kk + tg];
                af[mi][1] = ws[(mb + 8) * WS_S + kk + tg];
                af[mi][2] = ws[mb * WS_S + kk + tg + 4];
                af[mi][3] = ws[(mb + 8) * WS_S + kk + tg + 4];
            }
            #pragma unroll
            for (int ni = 0; ni < 2; ni++) {
                int nb = warp * 16 + ni * 8 + g;
                bf[ni][0] = hs[(kk + tg) * HS_S + nb];
                bf[ni][1] = hs[(kk + tg + 4) * HS_S + nb];
            }
            #pragma unroll
            for (int mi = 0; mi < 4; mi++)
                #pragma unroll
                for (int ni = 0; ni < 2; ni++)
                    mma8(acc[mi][ni], af[mi], bf[ni]);
        }
    }
    __syncthreads();

    #pragma unroll
    for (int mi = 0; mi < 4; mi++) {
        #pragma unroll
        for (int half = 0; half < 2; half++) {
            int row = i0 + mi * 16 + g + half * 8;
            if (row >= N) continue;
            float inv = 1.f / zrow[mi * 16 + g + half * 8];
            #pragma unroll
            for (int ni = 0; ni < 2; ni++) {
                int col = warp * 16 + ni * 8 + tg * 2;
                float v0 = acc[mi][ni][half * 2 + 0] * inv;
                float v1 = acc[mi][ni][half * 2 + 1] * inv;
                v0 = v0 > 0.f ? v0 : 0.f;
                v1 = v1 > 0.f ? v1 : 0.f;
                *(float2*)&j.out[(long)b * N * HH + (long)row * HH + col] = make_float2(v0, v1);
            }
        }
    }
}

// ---------------- merged helper kernels ----------------
struct SJob { const float* h; const float* a1; const float* a2;
              float* s1; float* s2; int N; int total; };

__global__ void scores2(SJob j0, SJob j1)
{
    SJob j; int bid;
    if (blockIdx.x < (unsigned)j0.total) { j = j0; bid = blockIdx.x; }
    else                                 { j = j1; bid = blockIdx.x - j0.total; }
    int nb = (j.N + 3) / 4;
    int b = bid / nb;
    int rb = bid - b * nb;
    int warp = threadIdx.x >> 5, lane = threadIdx.x & 31;
    int row = rb * 4 + warp;
    if (row >= j.N) return;
    const float* hr = j.h + ((long)b * j.N + row) * HH;
    float p1 = 0.f, p2 = 0.f;
    #pragma unroll
    for (int i = 0; i < 4; i++) {
        float hv = hr[lane + 32 * i];
        p1 += hv * j.a1[lane + 32 * i];
        p2 += hv * j.a2[lane + 32 * i];
    }
    #pragma unroll
    for (int off = 16; off; off >>= 1) {
        p1 += __shfl_xor_sync(0xffffffffu, p1, off);
        p2 += __shfl_xor_sync(0xffffffffu, p2, off);
    }
    if (lane == 0) {
        j.s1[(long)b * j.N + row] = p1;
        j.s2[(long)b * j.N + row] = p2;
    }
}

__global__ void smax2(const float* s2v, const float* s2o, float* smv, float* smo)
{
    __shared__ float red[256];
    int bx = blockIdx.x;
    const float* s2 = (bx < BB) ? s2v : s2o;
    float* sm       = (bx < BB) ? smv : smo;
    int N           = (bx < BB) ? NVV : NOO;
    int b           = (bx < BB) ? bx : bx - BB;
    float m = -1e30f;
    for (int i = threadIdx.x; i < N; i += 256) m = fmaxf(m, s2[(long)b * N + i]);
    red[threadIdx.x] = m;
    __syncthreads();
    for (int s = 128; s > 0; s >>= 1) {
        if (threadIdx.x < s) red[threadIdx.x] = fmaxf(red[threadIdx.x], red[threadIdx.x + s]);
        __syncthreads();
    }
    if (threadIdx.x == 0) sm[b] = red[0];
}

__global__ void colsum_kernel(const float* __restrict__ A, float* __restrict__ sums)
{
    int v = blockIdx.x * 256 + threadIdx.x;
    if (v >= NVV) return;
    int b = blockIdx.y, seg = blockIdx.z;
    const float* Ab = A + (long)b * NOO * NVV;
    int o0 = seg * 125;
    float s = 0.f;
    #pragma unroll 4
    for (int o = o0; o < o0 + 125; o++) s += Ab[(long)o * NVV + v];
    atomicAdd(&sums[b * NVV + v], s);
}

__global__ void rvfin_kernel(const float* __restrict__ sums, float* __restrict__ rv, int n)
{
    int i = blockIdx.x * 256 + threadIdx.x;
    if (i < n) rv[i] = 1.f / (sums[i] + EPSF);
}

__global__ void rowsum_kernel(const float* __restrict__ A, const float* __restrict__ rv,
                              float* __restrict__ to_)
{
    int warp = threadIdx.x >> 5, lane = threadIdx.x & 31;
    int o = blockIdx.x * 8 + warp;
    int b = blockIdx.y;
    if (o >= NOO) return;
    const float* Ar  = A + ((long)b * NOO + o) * NVV;
    const float* rvb = rv + b * NVV;
    float s = 0.f;
    for (int v = lane; v < NVV; v += 32) s += Ar[v] * rvb[v];
    #pragma unroll
    for (int off = 16; off; off >>= 1) s += __shfl_xor_sync(0xffffffffu, s, off);
    if (lane == 0) to_[b * NOO + o] = 1.f / (s + EPSF);
}

// ---------------- host orchestration ----------------
static GJob mkjob(bool transA, const float* A, const float* Bm, float* C,
                  const float* bias, const float* res, const float* rowscale,
                  const float* kscale, int M, int N, int K,
                  long sA, long sB, long sC, int relu, int G)
{
    GJob j;
    j.A = A; j.Bm = Bm; j.C = C; j.bias = bias; j.res = res;
    j.rowscale = rowscale; j.kscale = kscale;
    j.M = M; j.N = N; j.K = K; j.sA = sA; j.sB = sB; j.sC = sC;
    j.relu = relu; j.transA = transA ? 1 : 0;
    j.gx = (N + TBN - 1) / TBN;
    j.gy = (M + TBM - 1) / TBM;
    j.total = j.gx * j.gy * G;
    return j;
}

static void launch_gemm2(const GJob& a, const GJob& b)
{
    gemm_tc2<<<a.total + b.total, 128>>>(a, b);
}

extern "C" void kernel_launch(void* const* d_in, const int* in_sizes, int n_in,
                              void* d_out, int out_size)
{
    const float* vis_memory = (const float*)d_in[0];
    const float* obj_memory = (const float*)d_in[1];
    const float* vis_adj    = (const float*)d_in[2];
    const float* obj_adj    = (const float*)d_in[3];
    const float* A_OV       = (const float*)d_in[4];
    const float* Wv1  = (const float*)d_in[5];
    const float* av1a = (const float*)d_in[6];
    const float* av1b = (const float*)d_in[7];
    const float* Wv2  = (const float*)d_in[8];
    const float* av2a = (const float*)d_in[9];
    const float* av2b = (const float*)d_in[10];
    const float* Wo1  = (const float*)d_in[11];
    const float* ao1a = (const float*)d_in[12];
    const float* ao1b = (const float*)d_in[13];
    const float* Wo2  = (const float*)d_in[14];
    const float* ao2a = (const float*)d_in[15];
    const float* ao2b = (const float*)d_in[16];
    const float* g2o_W1 = (const float*)d_in[17];
    const float* g2o_b1 = (const float*)d_in[18];
    const float* g2o_W2 = (const float*)d_in[19];
    const float* g2o_b2 = (const float*)d_in[20];
    const float* o2g_W1 = (const float*)d_in[21];
    const float* o2g_b1 = (const float*)d_in[22];
    const float* o2g_W2 = (const float*)d_in[23];
    const float* o2g_b2 = (const float*)d_in[24];
    const float* img_W = (const float*)d_in[25];
    const float* img_b = (const float*)d_in[26];
    const float* obj_W = (const float*)d_in[27];
    const float* obj_b = (const float*)d_in[28];

    float *p_hv, *p_ho, *p_v, *p_o, *p_cv, *p_co, *p_m1v, *p_m1o, *p_vis, *p_obj;
    float *p_s1v, *p_s2v, *p_s1o, *p_s2o, *p_smaxv, *p_smaxo, *p_rvsum, *p_rv, *p_to;
    cudaGetSymbolAddress((void**)&p_hv,  g_hv);
    cudaGetSymbolAddress((void**)&p_ho,  g_ho);
    cudaGetSymbolAddress((void**)&p_v,   g_v);
    cudaGetSymbolAddress((void**)&p_o,   g_o);
    cudaGetSymbolAddress((void**)&p_cv,  g_cv);
    cudaGetSymbolAddress((void**)&p_co,  g_co);
    cudaGetSymbolAddress((void**)&p_m1v, g_m1v);
    cudaGetSymbolAddress((void**)&p_m1o, g_m1o);
    cudaGetSymbolAddress((void**)&p_vis, g_vis);
    cudaGetSymbolAddress((void**)&p_obj, g_obj);
    cudaGetSymbolAddress((void**)&p_s1v, g_s1v);
    cudaGetSymbolAddress((void**)&p_s2v, g_s2v);
    cudaGetSymbolAddress((void**)&p_s1o, g_s1o);
    cudaGetSymbolAddress((void**)&p_s2o, g_s2o);
    cudaGetSymbolAddress((void**)&p_smaxv, g_smaxv);
    cudaGetSymbolAddress((void**)&p_smaxo, g_smaxo);
    cudaGetSymbolAddress((void**)&p_rvsum, g_rvsum);
    cudaGetSymbolAddress((void**)&p_rv,  g_rv);
    cudaGetSymbolAddress((void**)&p_to,  g_to);

    cudaFuncSetAttribute(attn_tc2, cudaFuncAttributeMaxDynamicSharedMemorySize, ATTN_SMEM_TC);

    // cross-adjacency normalizers
    cudaMemsetAsync(p_rvsum, 0, BB * NVV * sizeof(float));
    colsum_kernel<<<dim3(2, BB, 12), 256>>>(A_OV, p_rvsum);
    rvfin_kernel<<<(BB * NVV + 255) / 256, 256>>>(p_rvsum, p_rv, BB * NVV);
    rowsum_kernel<<<dim3((NOO + 7) / 8, BB), 256>>>(A_OV, p_rv, p_to);

    for (int round = 0; round < 2; round++) {
        const float* xv  = (round == 0) ? vis_memory : p_vis;
        const float* xo  = (round == 0) ? obj_memory : p_obj;
        int Kv           = (round == 0) ? DVV : HH;
        int Ko           = (round == 0) ? DOO : HH;
        const float* Wv  = (round == 0) ? Wv1  : Wv2;
        const float* ava = (round == 0) ? av1a : av2a;
        const float* avb = (round == 0) ? av1b : av2b;
        const float* Wo  = (round == 0) ? Wo1  : Wo2;
        const float* aoa = (round == 0) ? ao1a : ao2a;
        const float* aob = (round == 0) ? ao1b : ao2b;

        // h = x @ W (flattened over batch), vis + obj merged
        launch_gemm2(
            mkjob(false, xv, Wv, p_hv, nullptr, nullptr, nullptr, nullptr,
                  BB * NVV, HH, Kv, 0, 0, 0, 0, 1),
            mkjob(false, xo, Wo, p_ho, nullptr, nullptr, nullptr, nullptr,
                  BB * NOO, HH, Ko, 0, 0, 0, 0, 1));

        // scores (merged) + per-batch max (merged)
        {
            SJob sv = { p_hv, ava, avb, p_s1v, p_s2v, NVV, ((NVV + 3) / 4) * BB };
            SJob so = { p_ho, aoa, aob, p_s1o, p_s2o, NOO, ((NOO + 3) / 4) * BB };
            scores2<<<sv.total + so.total, 128>>>(sv, so);
            smax2<<<2 * BB, 256>>>(p_s2v, p_s2o, p_smaxv, p_smaxo);
        }

        // fused masked softmax @ h + relu (merged)
        {
            int nxv = (NVV + AROWS - 1) / AROWS;
            int nxo = (NOO + AROWS - 1) / AROWS;
            AJob av_ = { p_hv, vis_adj, p_s1v, p_s2v, p_smaxv, p_v, NVV, nxv, nxv * BB };
            AJob ao_ = { p_ho, obj_adj, p_s1o, p_s2o, p_smaxo, p_o, NOO, nxo, nxo * BB };
            attn_tc2<<<av_.total + ao_.total, 256, ATTN_SMEM_TC>>>(av_, ao_);
        }

        // cv = rv ⊙ (A^T @ o)   ||   co = to ⊙ (A @ (rv ⊙ v))
        launch_gemm2(
            mkjob(true, A_OV, p_o, p_cv, nullptr, nullptr, p_rv, nullptr,
                  NVV, HH, NOO, (long)NOO * NVV, (long)NOO * HH, (long)NVV * HH, 0, BB),
            mkjob(false, A_OV, p_v, p_co, nullptr, nullptr, p_to, p_rv,
                  NOO, HH, NVV, (long)NOO * NVV, (long)NVV * HH, (long)NOO * HH, 0, BB));

        // mlp layer 1 (merged, relu)
        launch_gemm2(
            mkjob(false, p_cv, o2g_W1, p_m1v, o2g_b1, nullptr, nullptr, nullptr,
                  BB * NVV, HH, HH, 0, 0, 0, 1, 1),
            mkjob(false, p_co, g2o_W1, p_m1o, g2o_b1, nullptr, nullptr, nullptr,
                  BB * NOO, HH, HH, 0, 0, 0, 1, 1));

        // mlp layer 2 + residual (merged)
        launch_gemm2(
            mkjob(false, p_m1v, o2g_W2, p_vis, o2g_b2, p_v, nullptr, nullptr,
                  BB * NVV, HH, HH, 0, 0, 0, 0, 1),
            mkjob(false, p_m1o, g2o_W2, p_obj, g2o_b2, p_o, nullptr, nullptr,
                  BB * NOO, HH, HH, 0, 0, 0, 0, 1));
    }

    // output projections (merged)
    float* out_vis = (float*)d_out;
    float* out_obj = out_vis + (long)BB * NVV * DVV;
    launch_gemm2(
        mkjob(false, p_vis, img_W, out_vis, img_b, nullptr, nullptr, nullptr,
              BB * NVV, DVV, HH, 0, 0, 0, 0, 1),
        mkjob(false, p_obj, obj_W, out_obj, obj_b, nullptr, nullptr, nullptr,
              BB * NOO, DOO, HH, 0, 0, 0, 0, 1));
}

// round 5
// speedup vs baseline: 2.5168x; 1.0183x over previous
#include <cuda_runtime.h>
#include <math.h>

#define BB 8
#define NVV 500
#define NOO 1500
#define DVV 512
#define DOO 32
#define HH 128
#define EPSF 1e-5f

// ---------------- scratch ----------------
__device__ float g_hv [BB*NVV*HH];
__device__ float g_ho [BB*NOO*HH];
__device__ float g_v  [BB*NVV*HH];
__device__ float g_vsc[BB*NVV*HH];
__device__ float g_o  [BB*NOO*HH];
__device__ float g_cv [BB*NVV*HH];
__device__ float g_co [BB*NOO*HH];
__device__ float g_m1v[BB*NVV*HH];
__device__ float g_m1o[BB*NOO*HH];
__device__ float g_vis[BB*NVV*HH];
__device__ float g_obj[BB*NOO*HH];
__device__ float g_s1v[BB*NVV];
__device__ float g_s2v[BB*NVV];
__device__ float g_s1o[BB*NOO];
__device__ float g_s2o[BB*NOO];
__device__ float g_smaxv[BB];
__device__ float g_smaxo[BB];
__device__ float g_rvsum[BB*NVV];
__device__ float g_rv  [BB*NVV];
__device__ float g_to  [BB*NOO];

// ---------------- tf32 mma helpers ----------------
__device__ __forceinline__ unsigned cvt_tf32(float x) {
    unsigned r; asm("cvt.rna.tf32.f32 %0, %1;" : "=r"(r) : "f"(x)); return r;
}
// cheap RNA-to-tf32 via bit add (mma hw truncates low 13 bits)
__device__ __forceinline__ unsigned rnd13(unsigned x) { return x + 0x1000u; }

__device__ __forceinline__ void mma8(float* d, const unsigned* a, const unsigned* b) {
    asm volatile("mma.sync.aligned.m16n8k8.row.col.f32.tf32.tf32.f32 "
                 "{%0,%1,%2,%3},{%4,%5,%6,%7},{%8,%9},{%0,%1,%2,%3};"
                 : "+f"(d[0]), "+f"(d[1]), "+f"(d[2]), "+f"(d[3])
                 : "r"(a[0]), "r"(a[1]), "r"(a[2]), "r"(a[3]), "r"(b[0]), "r"(b[1]));
}

__device__ __forceinline__ void cpa16(unsigned dst, const void* src, int srcsz) {
    asm volatile("cp.async.cg.shared.global [%0], [%1], 16, %2;"
                 :: "r"(dst), "l"(src), "r"(srcsz));
}
__device__ __forceinline__ void cpa_commit() {
    asm volatile("cp.async.commit_group;");
}

// ---------------- dual-job tf32 GEMM: 64x64 tile, cp.async 4-stage ----------------
#define TBM 64
#define TBN 64
#define TBK 16
#define AST_T 72    // transA layout [k][m], stride 72 (8 mod 32 -> conflict-free)
#define AST_N 20    // non-trans layout [m][k], stride 20 (g*20 spreads banks)
#define BST   72
#define STAGES 4
#define AWORDS 1280 // max(64*20, 16*72)
#define BWORDS (16*72)

struct GJob {
    const float* A; const float* Bm; float* C;
    const float* bias; const float* res; const float* rowscale;
    int M, N, K; long sA, sB, sC;
    int relu, transA, gx, gy, total;
};

__device__ __forceinline__ void issue_tile(const GJob& j, const float* Ab, const float* Bb,
                                           int m0, int n0, int it,
                                           unsigned aBase, unsigned bBase, int t)
{
    int K = j.K, M = j.M, N = j.N;
    int k0 = it * TBK;
    if (j.transA) {
        int k = t >> 3;
        int gk = k0 + k;
        #pragma unroll
        for (int i = 0; i < 2; i++) {
            int m4 = ((t & 7) * 2 + i) * 4;
            int gm = m0 + m4;
            bool ok = (gk < K) && (gm < M);
            const float* src = ok ? &Ab[(long)gk * M + gm] : Ab;
            cpa16(aBase + (unsigned)(k * AST_T + m4) * 4u, src, ok ? 16 : 0);
        }
    } else {
        int m = t >> 1;
        int gm = m0 + m;
        #pragma unroll
        for (int i = 0; i < 2; i++) {
            int c = (t & 1) * 2 + i;
            int gk = k0 + c * 4;
            bool ok = (gm < M) && (gk < K);
            const float* src = ok ? &Ab[(long)gm * K + gk] : Ab;
            cpa16(aBase + (unsigned)(m * AST_N + c * 4) * 4u, src, ok ? 16 : 0);
        }
    }
    {
        int k = t >> 3;
        int gk = k0 + k;
        #pragma unroll
        for (int i = 0; i < 2; i++) {
            int n4 = ((t & 7) * 2 + i) * 4;
            int gn = n0 + n4;
            bool ok = (gk < K) && (gn < N);
            const float* src = ok ? &Bb[(long)gk * N + gn] : Bb;
            cpa16(bBase + (unsigned)(k * BST + n4) * 4u, src, ok ? 16 : 0);
        }
    }
}

__global__ void __launch_bounds__(128) gemm_tc3(GJob j0, GJob j1)
{
    __shared__ unsigned As[STAGES][AWORDS];
    __shared__ unsigned Bs[STAGES][BWORDS];

    GJob j; int bid;
    if (blockIdx.x < (unsigned)j0.total) { j = j0; bid = blockIdx.x; }
    else                                 { j = j1; bid = blockIdx.x - j0.total; }

    int per = j.gx * j.gy;
    int b   = bid / per;
    int rem = bid - b * per;
    int by  = rem / j.gx;
    int bx  = rem - by * j.gx;

    const float* Ab = j.A  + (long)b * j.sA;
    const float* Bb = j.Bm + (long)b * j.sB;
    int m0 = by * TBM, n0 = bx * TBN;
    int M = j.M, N = j.N, K = j.K;

    int t = threadIdx.x;
    int warp = t >> 5, lane = t & 31;
    int g = lane >> 2, tg = lane & 3;
    int wm = warp >> 1, wn = warp & 1;
    int transA = j.transA;

    float acc[2][4][4];
    #pragma unroll
    for (int mi = 0; mi < 2; mi++)
        #pragma unroll
        for (int ni = 0; ni < 4; ni++)
            #pragma unroll
            for (int e = 0; e < 4; e++) acc[mi][ni][e] = 0.f;

    int ntiles = (K + TBK - 1) / TBK;

    // prologue: STAGES-1 committed groups (possibly empty)
    #pragma unroll
    for (int s = 0; s < STAGES - 1; s++) {
        if (s < ntiles) {
            unsigned aB = (unsigned)__cvta_generic_to_shared(&As[s][0]);
            unsigned bB = (unsigned)__cvta_generic_to_shared(&Bs[s][0]);
            issue_tile(j, Ab, Bb, m0, n0, s, aB, bB, t);
        }
        cpa_commit();
    }

    for (int it = 0; it < ntiles; it++) {
        asm volatile("cp.async.wait_group %0;" :: "n"(STAGES - 2));
        __syncthreads();

        // issue tile it+STAGES-1 (overlaps compute); buffer (it-1)%S is free
        int nx = it + STAGES - 1;
        if (nx < ntiles) {
            unsigned aB = (unsigned)__cvta_generic_to_shared(&As[nx & (STAGES - 1)][0]);
            unsigned bB = (unsigned)__cvta_generic_to_shared(&Bs[nx & (STAGES - 1)][0]);
            issue_tile(j, Ab, Bb, m0, n0, nx, aB, bB, t);
        }
        cpa_commit();

        const unsigned* Asb = As[it & (STAGES - 1)];
        const unsigned* Bsb = Bs[it & (STAGES - 1)];

        #pragma unroll
        for (int kk = 0; kk < TBK; kk += 8) {
            unsigned af[2][4], bf[4][2];
            if (transA) {
                #pragma unroll
                for (int mi = 0; mi < 2; mi++) {
                    int mb = wm * 32 + mi * 16 + g;
                    af[mi][0] = rnd13(Asb[(kk + tg) * AST_T + mb]);
                    af[mi][1] = rnd13(Asb[(kk + tg) * AST_T + mb + 8]);
                    af[mi][2] = rnd13(Asb[(kk + tg + 4) * AST_T + mb]);
                    af[mi][3] = rnd13(Asb[(kk + tg + 4) * AST_T + mb + 8]);
                }
            } else {
                #pragma unroll
                for (int mi = 0; mi < 2; mi++) {
                    int mb = wm * 32 + mi * 16 + g;
                    af[mi][0] = rnd13(Asb[mb * AST_N + kk + tg]);
                    af[mi][1] = rnd13(Asb[(mb + 8) * AST_N + kk + tg]);
                    af[mi][2] = rnd13(Asb[mb * AST_N + kk + tg + 4]);
                    af[mi][3] = rnd13(Asb[(mb + 8) * AST_N + kk + tg + 4]);
                }
            }
            #pragma unroll
            for (int ni = 0; ni < 4; ni++) {
                int nb = wn * 32 + ni * 8 + g;
                bf[ni][0] = rnd13(Bsb[(kk + tg) * BST + nb]);
                bf[ni][1] = rnd13(Bsb[(kk + tg + 4) * BST + nb]);
            }
            #pragma unroll
            for (int mi = 0; mi < 2; mi++)
                #pragma unroll
                for (int ni = 0; ni < 4; ni++)
                    mma8(acc[mi][ni], af[mi], bf[ni]);
        }
    }

    // epilogue
    #pragma unroll
    for (int mi = 0; mi < 2; mi++) {
        #pragma unroll
        for (int half = 0; half < 2; half++) {
            int row = m0 + wm * 32 + mi * 16 + g + half * 8;
            if (row >= M) continue;
            float scale = j.rowscale ? j.rowscale[b * M + row] : 1.f;
            #pragma unroll
            for (int ni = 0; ni < 4; ni++) {
                int col = n0 + wn * 32 + ni * 8 + tg * 2;
                if (col >= N) continue;
                float v0 = acc[mi][ni][half * 2 + 0] * scale;
                float v1 = acc[mi][ni][half * 2 + 1] * scale;
                if (j.bias) { v0 += j.bias[col]; v1 += j.bias[col + 1]; }
                long off = (long)b * j.sC + (long)row * N + col;
                if (j.res) { v0 += j.res[off]; v1 += j.res[off + 1]; }
                if (j.relu) { v0 = v0 > 0.f ? v0 : 0.f; v1 = v1 > 0.f ? v1 : 0.f; }
                *(float2*)&j.C[off] = make_float2(v0, v1);
            }
        }
    }
}

// ---------------- dual-job fused masked-softmax attention ----------------
#define AROWS 64
#define AJC 128
#define HS_S 136
#define WS_S 132
#define ATTN_SMEM_TC ((128*HS_S + AROWS*WS_S + AROWS) * 4)

struct AJob {
    const float* h; const float* adj; const float* s1; const float* s2;
    const float* smax; float* out; float* out2; const float* rowsc;
    int N; int nx; int total;
};

__global__ void __launch_bounds__(256) attn_tc2(AJob j0, AJob j1)
{
    extern __shared__ unsigned smu[];
    unsigned* hs = smu;                       // [128][HS_S]
    unsigned* ws = smu + 128 * HS_S;          // [AROWS][WS_S]
    float* zrow  = (float*)(ws + AROWS * WS_S);

    AJob j; int bid;
    if (blockIdx.x < (unsigned)j0.total) { j = j0; bid = blockIdx.x; }
    else                                 { j = j1; bid = blockIdx.x - j0.total; }
    int b  = bid / j.nx;
    int i0 = (bid - b * j.nx) * AROWS;
    int N  = j.N;

    int t = threadIdx.x;
    int warp = t >> 5, lane = t & 31;
    int g = lane >> 2, tg = lane & 3;

    const float* hb   = j.h   + (long)b * N * HH;
    const float* adjb = j.adj + (long)b * N * N;
    const float* s2b  = j.s2  + (long)b * N;

    float acc[4][2][4];
    #pragma unroll
    for (int mi = 0; mi < 4; mi++)
        #pragma unroll
        for (int ni = 0; ni < 2; ni++)
            #pragma unroll
            for (int e = 0; e < 4; e++) acc[mi][ni][e] = 0.f;

    if (t < AROWS) zrow[t] = 0.f;

    int pr = t >> 2;
    int pj = (t & 3) * 32;
    int prow = i0 + pr;
    float s1r = 0.f, mrow = 0.f;
    if (prow < N) {
        s1r = j.s1[(long)b * N + prow];
        float x = s1r + j.smax[b];
        mrow = x > 0.f ? x : 0.2f * x;
    }

    int hrow0 = t >> 5;
    int hf4 = (t & 31) * 4;

    for (int c0 = 0; c0 < N; c0 += AJC) {
        __syncthreads();

        // stage h chunk
        #pragma unroll
        for (int q = 0; q < 16; q++) {
            int jj = hrow0 + q * 8;
            int gj = c0 + jj;
            uint4 u;
            if (gj < N) {
                float4 v = *(const float4*)&hb[(long)gj * HH + hf4];
                u.x = cvt_tf32(v.x); u.y = cvt_tf32(v.y);
                u.z = cvt_tf32(v.z); u.w = cvt_tf32(v.w);
            } else {
                u = make_uint4(0, 0, 0, 0);
            }
            *(uint4*)&hs[jj * HS_S + hf4] = u;
        }

        // weight tile + partial z
        float zl = 0.f;
        if (prow < N) {
            const float* arow = adjb + (long)prow * N + c0;
            #pragma unroll
            for (int q4 = 0; q4 < 32; q4 += 4) {
                int jj = pj + q4;
                int gj = c0 + jj;
                float a[4], s[4];
                if (gj + 3 < N) {
                    float4 a4 = *(const float4*)&arow[jj];
                    float4 s4 = *(const float4*)&s2b[gj];
                    a[0]=a4.x; a[1]=a4.y; a[2]=a4.z; a[3]=a4.w;
                    s[0]=s4.x; s[1]=s4.y; s[2]=s4.z; s[3]=s4.w;
                } else {
                    #pragma unroll
                    for (int e = 0; e < 4; e++) {
                        bool ok = (gj + e) < N;
                        a[e] = ok ? arow[jj + e] : 0.f;
                        s[e] = ok ? s2b[gj + e] : 0.f;
                    }
                }
                #pragma unroll
                for (int e = 0; e < 4; e++) {
                    float w = 0.f;
                    if (a[e] > 0.f) {
                        float x = s1r + s[e];
                        float ev = x > 0.f ? x : 0.2f * x;
                        w = __expf(ev - mrow);
                    }
                    unsigned wu = cvt_tf32(w);
                    ws[pr * WS_S + jj + e] = wu;
                    zl += __uint_as_float(wu);
                }
            }
        } else {
            #pragma unroll 8
            for (int q = 0; q < 32; q++) ws[pr * WS_S + pj + q] = 0u;
        }
        zl += __shfl_down_sync(0xffffffffu, zl, 2);
        zl += __shfl_down_sync(0xffffffffu, zl, 1);
        if ((t & 3) == 0 && prow < N) zrow[pr] += zl;
        __syncthreads();

        // acc += ws(64x128) @ hs(128x128)
        #pragma unroll
        for (int kk = 0; kk < AJC; kk += 8) {
            unsigned af[4][4], bf[2][2];
            #pragma unroll
            for (int mi = 0; mi < 4; mi++) {
                int mb = mi * 16 + g;
                af[mi][0] = ws[mb * WS_S + kk + tg];
                af[mi][1] = ws[(mb + 8) * WS_S + kk + tg];
                af[mi][2] = ws[mb * WS_S + kk + tg + 4];
                af[mi][3] = ws[(mb + 8) * WS_S + kk + tg + 4];
            }
            #pragma unroll
            for (int ni = 0; ni < 2; ni++) {
                int nb = warp * 16 + ni * 8 + g;
                bf[ni][0] = hs[(kk + tg) * HS_S + nb];
                bf[ni][1] = hs[(kk + tg + 4) * HS_S + nb];
            }
            #pragma unroll
            for (int mi = 0; mi < 4; mi++)
                #pragma unroll
                for (int ni = 0; ni < 2; ni++)
                    mma8(acc[mi][ni], af[mi], bf[ni]);
        }
    }
    __syncthreads();

    #pragma unroll
    for (int mi = 0; mi < 4; mi++) {
        #pragma unroll
        for (int half = 0; half < 2; half++) {
            int row = i0 + mi * 16 + g + half * 8;
            if (row >= N) continue;
            float inv = 1.f / zrow[mi * 16 + g + half * 8];
            float rs = j.out2 ? j.rowsc[(long)b * N + row] : 0.f;
            #pragma unroll
            for (int ni = 0; ni < 2; ni++) {
                int col = warp * 16 + ni * 8 + tg * 2;
                float v0 = acc[mi][ni][half * 2 + 0] * inv;
                float v1 = acc[mi][ni][half * 2 + 1] * inv;
                v0 = v0 > 0.f ? v0 : 0.f;
                v1 = v1 > 0.f ? v1 : 0.f;
                long off = (long)b * N * HH + (long)row * HH + col;
                *(float2*)&j.out[off] = make_float2(v0, v1);
                if (j.out2)
                    *(float2*)&j.out2[off] = make_float2(v0 * rs, v1 * rs);
            }
        }
    }
}

// ---------------- merged helper kernels ----------------
struct SJob { const float* h; const float* a1; const float* a2;
              float* s1; float* s2; int N; int total; };

__global__ void scores2(SJob j0, SJob j1)
{
    SJob j; int bid;
    if (blockIdx.x < (unsigned)j0.total) { j = j0; bid = blockIdx.x; }
    else                                 { j = j1; bid = blockIdx.x - j0.total; }
    int nb = (j.N + 3) / 4;
    int b = bid / nb;
    int rb = bid - b * nb;
    int warp = threadIdx.x >> 5, lane = threadIdx.x & 31;
    int row = rb * 4 + warp;
    if (row >= j.N) return;
    const float* hr = j.h + ((long)b * j.N + row) * HH;
    float p1 = 0.f, p2 = 0.f;
    #pragma unroll
    for (int i = 0; i < 4; i++) {
        float hv = hr[lane + 32 * i];
        p1 += hv * j.a1[lane + 32 * i];
        p2 += hv * j.a2[lane + 32 * i];
    }
    #pragma unroll
    for (int off = 16; off; off >>= 1) {
        p1 += __shfl_xor_sync(0xffffffffu, p1, off);
        p2 += __shfl_xor_sync(0xffffffffu, p2, off);
    }
    if (lane == 0) {
        j.s1[(long)b * j.N + row] = p1;
        j.s2[(long)b * j.N + row] = p2;
    }
}

__global__ void smax2(const float* s2v, const float* s2o, float* smv, float* smo)
{
    __shared__ float red[256];
    int bx = blockIdx.x;
    const float* s2 = (bx < BB) ? s2v : s2o;
    float* sm       = (bx < BB) ? smv : smo;
    int N           = (bx < BB) ? NVV : NOO;
    int b           = (bx < BB) ? bx : bx - BB;
    float m = -1e30f;
    for (int i = threadIdx.x; i < N; i += 256) m = fmaxf(m, s2[(long)b * N + i]);
    red[threadIdx.x] = m;
    __syncthreads();
    for (int s = 128; s > 0; s >>= 1) {
        if (threadIdx.x < s) red[threadIdx.x] = fmaxf(red[threadIdx.x], red[threadIdx.x + s]);
        __syncthreads();
    }
    if (threadIdx.x == 0) sm[b] = red[0];
}

__global__ void colsum_kernel(const float* __restrict__ A, float* __restrict__ sums)
{
    int v = blockIdx.x * 256 + threadIdx.x;
    if (v >= NVV) return;
    int b = blockIdx.y, seg = blockIdx.z;
    const float* Ab = A + (long)b * NOO * NVV;
    int o0 = seg * 125;
    float s = 0.f;
    #pragma unroll 4
    for (int o = o0; o < o0 + 125; o++) s += Ab[(long)o * NVV + v];
    atomicAdd(&sums[b * NVV + v], s);
}

__global__ void rvfin_kernel(const float* __restrict__ sums, float* __restrict__ rv, int n)
{
    int i = blockIdx.x * 256 + threadIdx.x;
    if (i < n) rv[i] = 1.f / (sums[i] + EPSF);
}

__global__ void rowsum_kernel(const float* __restrict__ A, const float* __restrict__ rv,
                              float* __restrict__ to_)
{
    int warp = threadIdx.x >> 5, lane = threadIdx.x & 31;
    int o = blockIdx.x * 8 + warp;
    int b = blockIdx.y;
    if (o >= NOO) return;
    const float* Ar  = A + ((long)b * NOO + o) * NVV;
    const float* rvb = rv + b * NVV;
    float s = 0.f;
    for (int v = lane; v < NVV; v += 32) s += Ar[v] * rvb[v];
    #pragma unroll
    for (int off = 16; off; off >>= 1) s += __shfl_xor_sync(0xffffffffu, s, off);
    if (lane == 0) to_[b * NOO + o] = 1.f / (s + EPSF);
}

// ---------------- host orchestration ----------------
static GJob mkjob(bool transA, const float* A, const float* Bm, float* C,
                  const float* bias, const float* res, const float* rowscale,
                  int M, int N, int K, long sA, long sB, long sC, int relu, int G)
{
    GJob j;
    j.A = A; j.Bm = Bm; j.C = C; j.bias = bias; j.res = res;
    j.rowscale = rowscale;
    j.M = M; j.N = N; j.K = K; j.sA = sA; j.sB = sB; j.sC = sC;
    j.relu = relu; j.transA = transA ? 1 : 0;
    j.gx = (N + TBN - 1) / TBN;
    j.gy = (M + TBM - 1) / TBM;
    j.total = j.gx * j.gy * G;
    return j;
}

static void launch_gemm2(const GJob& a, const GJob& b)
{
    gemm_tc3<<<a.total + b.total, 128>>>(a, b);
}

extern "C" void kernel_launch(void* const* d_in, const int* in_sizes, int n_in,
                              void* d_out, int out_size)
{
    const float* vis_memory = (const float*)d_in[0];
    const float* obj_memory = (const float*)d_in[1];
    const float* vis_adj    = (const float*)d_in[2];
    const float* obj_adj    = (const float*)d_in[3];
    const float* A_OV       = (const float*)d_in[4];
    const float* Wv1  = (const float*)d_in[5];
    const float* av1a = (const float*)d_in[6];
    const float* av1b = (const float*)d_in[7];
    const float* Wv2  = (const float*)d_in[8];
    const float* av2a = (const float*)d_in[9];
    const float* av2b = (const float*)d_in[10];
    const float* Wo1  = (const float*)d_in[11];
    const float* ao1a = (const float*)d_in[12];
    const float* ao1b = (const float*)d_in[13];
    const float* Wo2  = (const float*)d_in[14];
    const float* ao2a = (const float*)d_in[15];
    const float* ao2b = (const float*)d_in[16];
    const float* g2o_W1 = (const float*)d_in[17];
    const float* g2o_b1 = (const float*)d_in[18];
    const float* g2o_W2 = (const float*)d_in[19];
    const float* g2o_b2 = (const float*)d_in[20];
    const float* o2g_W1 = (const float*)d_in[21];
    const float* o2g_b1 = (const float*)d_in[22];
    const float* o2g_W2 = (const float*)d_in[23];
    const float* o2g_b2 = (const float*)d_in[24];
    const float* img_W = (const float*)d_in[25];
    const float* img_b = (const float*)d_in[26];
    const float* obj_W = (const float*)d_in[27];
    const float* obj_b = (const float*)d_in[28];

    float *p_hv, *p_ho, *p_v, *p_vsc, *p_o, *p_cv, *p_co, *p_m1v, *p_m1o, *p_vis, *p_obj;
    float *p_s1v, *p_s2v, *p_s1o, *p_s2o, *p_smaxv, *p_smaxo, *p_rvsum, *p_rv, *p_to;
    cudaGetSymbolAddress((void**)&p_hv,  g_hv);
    cudaGetSymbolAddress((void**)&p_ho,  g_ho);
    cudaGetSymbolAddress((void**)&p_v,   g_v);
    cudaGetSymbolAddress((void**)&p_vsc, g_vsc);
    cudaGetSymbolAddress((void**)&p_o,   g_o);
    cudaGetSymbolAddress((void**)&p_cv,  g_cv);
    cudaGetSymbolAddress((void**)&p_co,  g_co);
    cudaGetSymbolAddress((void**)&p_m1v, g_m1v);
    cudaGetSymbolAddress((void**)&p_m1o, g_m1o);
    cudaGetSymbolAddress((void**)&p_vis, g_vis);
    cudaGetSymbolAddress((void**)&p_obj, g_obj);
    cudaGetSymbolAddress((void**)&p_s1v, g_s1v);
    cudaGetSymbolAddress((void**)&p_s2v, g_s2v);
    cudaGetSymbolAddress((void**)&p_s1o, g_s1o);
    cudaGetSymbolAddress((void**)&p_s2o, g_s2o);
    cudaGetSymbolAddress((void**)&p_smaxv, g_smaxv);
    cudaGetSymbolAddress((void**)&p_smaxo, g_smaxo);
    cudaGetSymbolAddress((void**)&p_rvsum, g_rvsum);
    cudaGetSymbolAddress((void**)&p_rv,  g_rv);
    cudaGetSymbolAddress((void**)&p_to,  g_to);

    cudaFuncSetAttribute(attn_tc2, cudaFuncAttributeMaxDynamicSharedMemorySize, ATTN_SMEM_TC);

    // cross-adjacency normalizers
    cudaMemsetAsync(p_rvsum, 0, BB * NVV * sizeof(float));
    colsum_kernel<<<dim3(2, BB, 12), 256>>>(A_OV, p_rvsum);
    rvfin_kernel<<<(BB * NVV + 255) / 256, 256>>>(p_rvsum, p_rv, BB * NVV);
    rowsum_kernel<<<dim3((NOO + 7) / 8, BB), 256>>>(A_OV, p_rv, p_to);

    for (int round = 0; round < 2; round++) {
        const float* xv  = (round == 0) ? vis_memory : p_vis;
        const float* xo  = (round == 0) ? obj_memory : p_obj;
        int Kv           = (round == 0) ? DVV : HH;
        int Ko           = (round == 0) ? DOO : HH;
        const float* Wv  = (round == 0) ? Wv1  : Wv2;
        const float* ava = (round == 0) ? av1a : av2a;
        const float* avb = (round == 0) ? av1b : av2b;
        const float* Wo  = (round == 0) ? Wo1  : Wo2;
        const float* aoa = (round == 0) ? ao1a : ao2a;
        const float* aob = (round == 0) ? ao1b : ao2b;

        // h = x @ W (flattened over batch), vis + obj merged
        launch_gemm2(
            mkjob(false, xv, Wv, p_hv, nullptr, nullptr, nullptr,
                  BB * NVV, HH, Kv, 0, 0, 0, 0, 1),
            mkjob(false, xo, Wo, p_ho, nullptr, nullptr, nullptr,
                  BB * NOO, HH, Ko, 0, 0, 0, 0, 1));

        // scores (merged) + per-batch max (merged)
        {
            SJob sv = { p_hv, ava, avb, p_s1v, p_s2v, NVV, ((NVV + 3) / 4) * BB };
            SJob so = { p_ho, aoa, aob, p_s1o, p_s2o, NOO, ((NOO + 3) / 4) * BB };
            scores2<<<sv.total + so.total, 128>>>(sv, so);
            smax2<<<2 * BB, 256>>>(p_s2v, p_s2o, p_smaxv, p_smaxo);
        }

        // fused masked softmax @ h + relu (merged); vis job also writes rv-scaled copy
        {
            int nxv = (NVV + AROWS - 1) / AROWS;
            int nxo = (NOO + AROWS - 1) / AROWS;
            AJob av_ = { p_hv, vis_adj, p_s1v, p_s2v, p_smaxv, p_v, p_vsc, p_rv,
                         NVV, nxv, nxv * BB };
            AJob ao_ = { p_ho, obj_adj, p_s1o, p_s2o, p_smaxo, p_o, nullptr, nullptr,
                         NOO, nxo, nxo * BB };
            attn_tc2<<<av_.total + ao_.total, 256, ATTN_SMEM_TC>>>(av_, ao_);
        }

        // cv = rv ⊙ (A^T @ o)   ||   co = to ⊙ (A @ (rv ⊙ v))   [vsc pre-scaled]
        launch_gemm2(
            mkjob(true, A_OV, p_o, p_cv, nullptr, nullptr, p_rv,
                  NVV, HH, NOO, (long)NOO * NVV, (long)NOO * HH, (long)NVV * HH, 0, BB),
            mkjob(false, A_OV, p_vsc, p_co, nullptr, nullptr, p_to,
                  NOO, HH, NVV, (long)NOO * NVV, (long)NVV * HH, (long)NOO * HH, 0, BB));

        // mlp layer 1 (merged, relu)
        launch_gemm2(
            mkjob(false, p_cv, o2g_W1, p_m1v, o2g_b1, nullptr, nullptr,
                  BB * NVV, HH, HH, 0, 0, 0, 1, 1),
            mkjob(false, p_co, g2o_W1, p_m1o, g2o_b1, nullptr, nullptr,
                  BB * NOO, HH, HH, 0, 0, 0, 1, 1));

        // mlp layer 2 + residual (merged)
        launch_gemm2(
            mkjob(false, p_m1v, o2g_W2, p_vis, o2g_b2, p_v, nullptr,
                  BB * NVV, HH, HH, 0, 0, 0, 0, 1),
            mkjob(false, p_m1o, g2o_W2, p_obj, g2o_b2, p_o, nullptr,
                  BB * NOO, HH, HH, 0, 0, 0, 0, 1));
    }

    // output projections (merged)
    float* out_vis = (float*)d_out;
    float* out_obj = out_vis + (long)BB * NVV * DVV;
    launch_gemm2(
        mkjob(false, p_vis, img_W, out_vis, img_b, nullptr, nullptr,
              BB * NVV, DVV, HH, 0, 0, 0, 0, 1),
        mkjob(false, p_obj, obj_W, out_obj, obj_b, nullptr, nullptr,
              BB * NOO, DOO, HH, 0, 0, 0, 0, 1));
}